// round 2
// baseline (speedup 1.0000x reference)
#include <cuda_runtime.h>

// ---------------- problem dims ----------------
#define B_ROWS 16384
#define D_IN   1024
#define H1DIM  2048
#define H2DIM  1024
#define D_CODE 256
#define K_CODES 1024

// output layout (f32, concatenated): recon | quantized_st | loss | indices
#define RECON_ELEMS ((long long)B_ROWS * D_IN)          // 16777216
#define QST_OFF     (16777216)
#define LOSS_OFF    (16777216 + 4194304)                // 20971520
#define IDX_OFF     (20971521)

// ---------------- scratch (device globals; no allocation allowed) ----------------
__device__ float g_h1[B_ROWS * H1DIM];    // 128 MB, also decoder hidden-2
__device__ float g_h2[B_ROWS * H2DIM];    // 64 MB, also decoder hidden-1
__device__ float g_z [B_ROWS * D_CODE];   // 16 MB
__device__ float g_S [B_ROWS * K_CODES];  // 64 MB  (z @ codebook^T)
__device__ float g_cnorm[K_CODES];
__device__ float g_znorm[B_ROWS];
__device__ float g_rowloss[B_ROWS];

// ---------------- SGEMM: C[M,N] = act(A[M,K] @ B + bias) ----------------
// B row-major [K,N], or TRANSB: B row-major [N,K] (C = A @ B^T)
template<bool RELU, bool TRANSB, bool BIAS>
__global__ __launch_bounds__(256, 2)
void sgemm_kernel(const float* __restrict__ A, const float* __restrict__ Bm,
                  const float* __restrict__ bias, float* __restrict__ C,
                  int M, int N, int K)
{
    const int BM = 128, BN = 128, BK = 16;
    __shared__ float As[BK][BM + 4];
    __shared__ float Bs[BK][BN + 4];

    const int bm = blockIdx.y * BM;
    const int bn = blockIdx.x * BN;
    const int tid = threadIdx.x;

    const int tr = (tid / 16) * 8;   // row of 8x8 microtile within block tile
    const int tc = (tid % 16) * 8;   // col

    float acc[8][8];
#pragma unroll
    for (int i = 0; i < 8; i++)
#pragma unroll
        for (int j = 0; j < 8; j++) acc[i][j] = 0.0f;

    // A-tile loader: 128x16 floats as float4; 64 rows per step, 2 steps
    const int arow = tid >> 2;          // 0..63
    const int acol = (tid & 3) * 4;     // 0,4,8,12
    // B-tile loader (no trans): 16x128; 8 rows per step, 2 steps
    const int brow = tid >> 5;          // 0..7
    const int bcol = (tid & 31) * 4;
    // B-tile loader (trans): reads B[N,K]; 64 n-rows per step
    const int trow = tid >> 2;          // 0..63 (n)
    const int tcol = (tid & 3) * 4;     // k

    for (int k0 = 0; k0 < K; k0 += BK) {
#pragma unroll
        for (int s = 0; s < 2; s++) {
            const int r = arow + s * 64;
            float4 v = *(const float4*)&A[(long long)(bm + r) * K + k0 + acol];
            As[acol + 0][r] = v.x;
            As[acol + 1][r] = v.y;
            As[acol + 2][r] = v.z;
            As[acol + 3][r] = v.w;
        }
        if (!TRANSB) {
#pragma unroll
            for (int s = 0; s < 2; s++) {
                const int r = brow + s * 8;
                float4 v = *(const float4*)&Bm[(long long)(k0 + r) * N + bn + bcol];
                *(float4*)&Bs[r][bcol] = v;
            }
        } else {
#pragma unroll
            for (int s = 0; s < 2; s++) {
                const int n = trow + s * 64;
                float4 v = *(const float4*)&Bm[(long long)(bn + n) * K + k0 + tcol];
                Bs[tcol + 0][n] = v.x;
                Bs[tcol + 1][n] = v.y;
                Bs[tcol + 2][n] = v.z;
                Bs[tcol + 3][n] = v.w;
            }
        }
        __syncthreads();

#pragma unroll
        for (int kk = 0; kk < BK; kk++) {
            float ra[8], rb[8];
#pragma unroll
            for (int i = 0; i < 8; i++) ra[i] = As[kk][tr + i];
#pragma unroll
            for (int j = 0; j < 8; j++) rb[j] = Bs[kk][tc + j];
#pragma unroll
            for (int i = 0; i < 8; i++)
#pragma unroll
                for (int j = 0; j < 8; j++)
                    acc[i][j] = fmaf(ra[i], rb[j], acc[i][j]);
        }
        __syncthreads();
    }

    // epilogue: bias + relu, vectorized stores
#pragma unroll
    for (int i = 0; i < 8; i++) {
        const long long row = bm + tr + i;
#pragma unroll
        for (int j = 0; j < 8; j += 4) {
            float4 v;
            v.x = acc[i][j + 0];
            v.y = acc[i][j + 1];
            v.z = acc[i][j + 2];
            v.w = acc[i][j + 3];
            if (BIAS) {
                const int c = bn + tc + j;
                v.x += bias[c + 0];
                v.y += bias[c + 1];
                v.z += bias[c + 2];
                v.w += bias[c + 3];
            }
            if (RELU) {
                v.x = fmaxf(v.x, 0.0f);
                v.y = fmaxf(v.y, 0.0f);
                v.z = fmaxf(v.z, 0.0f);
                v.w = fmaxf(v.w, 0.0f);
            }
            *(float4*)&C[row * N + bn + tc + j] = v;
        }
    }
}

// ---------------- row squared-norms for 256-wide rows (warp per row) ----------------
__global__ void rownorm256_kernel(const float* __restrict__ X, float* __restrict__ out,
                                  int rows)
{
    const int gw = (blockIdx.x * blockDim.x + threadIdx.x) >> 5;
    const int lane = threadIdx.x & 31;
    if (gw >= rows) return;
    const float* r = X + (long long)gw * 256;
    float a = 0.0f;
#pragma unroll
    for (int i = 0; i < 8; i++) {
        float v = r[lane + i * 32];
        a = fmaf(v, v, a);
    }
#pragma unroll
    for (int o = 16; o > 0; o >>= 1) a += __shfl_xor_sync(0xffffffffu, a, o);
    if (lane == 0) out[gw] = a;
}

// ---------------- argmin over codes + gather + straight-through + row loss ----------------
// score_k = (znorm_b + cnorm_k) - 2*S[b,k]   (matches reference formula/rounding shape)
__global__ void argmin_quant_kernel(const float* __restrict__ S,
                                    const float* __restrict__ z,
                                    const float* __restrict__ codebook,
                                    const float* __restrict__ cnorm,
                                    const float* __restrict__ znorm,
                                    float* __restrict__ out_qst,   // d_out + QST_OFF
                                    float* __restrict__ out_idx,   // d_out + IDX_OFF
                                    float* __restrict__ rowloss)
{
    const int b = blockIdx.x;
    const int tid = threadIdx.x;   // 256 threads
    const float zn = znorm[b];

    float bestv = __int_as_float(0x7f800000);  // +inf
    int besti = 0x7fffffff;
#pragma unroll
    for (int s = 0; s < K_CODES / 256; s++) {
        const int k = tid + s * 256;
        const float t = zn + cnorm[k];
        const float score = t - 2.0f * S[(long long)b * K_CODES + k];
        if (score < bestv) { bestv = score; besti = k; }
    }

    __shared__ float sv[256];
    __shared__ int   si[256];
    sv[tid] = bestv; si[tid] = besti;
    __syncthreads();
#pragma unroll
    for (int s = 128; s > 0; s >>= 1) {
        if (tid < s) {
            const float v2 = sv[tid + s];
            const int   i2 = si[tid + s];
            if (v2 < sv[tid] || (v2 == sv[tid] && i2 < si[tid])) {
                sv[tid] = v2; si[tid] = i2;
            }
        }
        __syncthreads();
    }
    const int idx = si[0];
    if (tid == 0) out_idx[b] = (float)idx;

    // gather + straight-through + per-row loss (tid indexes the 256 code dims)
    const float q = codebook[(long long)idx * D_CODE + tid];
    const float zv = z[(long long)b * D_CODE + tid];
    const float d = q - zv;                  // stop_gradient(quantized - z) value
    out_qst[(long long)b * D_CODE + tid] = zv + d;  // z + (q - z), matches reference rounding
    __syncthreads();
    sv[tid] = d * d;
    __syncthreads();
#pragma unroll
    for (int s = 128; s > 0; s >>= 1) {
        if (tid < s) sv[tid] += sv[tid + s];
        __syncthreads();
    }
    if (tid == 0) rowloss[b] = sv[0];
}

__global__ void loss_final_kernel(const float* __restrict__ rowloss,
                                  float* __restrict__ out_loss)
{
    __shared__ float s[1024];
    const int tid = threadIdx.x;
    float a = 0.0f;
    for (int i = tid; i < B_ROWS; i += 1024) a += rowloss[i];
    s[tid] = a;
    __syncthreads();
#pragma unroll
    for (int t = 512; t > 0; t >>= 1) {
        if (tid < t) s[tid] += s[tid + t];
        __syncthreads();
    }
    // loss = q_latent + 0.25*e_latent = 1.25 * mean((q-z)^2)
    if (tid == 0) *out_loss = s[0] * (1.25f / (float)(B_ROWS * D_CODE));
}

// ---------------- launch ----------------
static inline float* sym(const void* s) {
    void* p = nullptr;
    cudaGetSymbolAddress(&p, s);
    return (float*)p;
}

extern "C" void kernel_launch(void* const* d_in, const int* in_sizes, int n_in,
                              void* d_out, int out_size)
{
    const float* x    = (const float*)d_in[0];
    const float* eW1  = (const float*)d_in[1];
    const float* eb1  = (const float*)d_in[2];
    const float* eW2  = (const float*)d_in[3];
    const float* eb2  = (const float*)d_in[4];
    const float* eW3  = (const float*)d_in[5];
    const float* eb3  = (const float*)d_in[6];
    const float* cb   = (const float*)d_in[7];
    const float* dW1  = (const float*)d_in[8];
    const float* db1  = (const float*)d_in[9];
    const float* dW2  = (const float*)d_in[10];
    const float* db2  = (const float*)d_in[11];
    const float* dW3  = (const float*)d_in[12];
    const float* db3  = (const float*)d_in[13];

    float* out   = (float*)d_out;
    float* recon = out;
    float* qst   = out + QST_OFF;
    float* lossp = out + LOSS_OFF;
    float* idxp  = out + IDX_OFF;

    float* h1 = sym(g_h1);
    float* h2 = sym(g_h2);
    float* z  = sym(g_z);
    float* S  = sym(g_S);
    float* cn = sym(g_cnorm);
    float* zn = sym(g_znorm);
    float* rl = sym(g_rowloss);

    dim3 blk(256);

    // encoder
    sgemm_kernel<true,  false, true><<<dim3(H1DIM/128, B_ROWS/128), blk>>>(x,  eW1, eb1, h1, B_ROWS, H1DIM, D_IN);
    sgemm_kernel<true,  false, true><<<dim3(H2DIM/128, B_ROWS/128), blk>>>(h1, eW2, eb2, h2, B_ROWS, H2DIM, H1DIM);
    sgemm_kernel<false, false, true><<<dim3(D_CODE/128, B_ROWS/128), blk>>>(h2, eW3, eb3, z, B_ROWS, D_CODE, H2DIM);

    // norms
    rownorm256_kernel<<<K_CODES * 32 / 256, 256>>>(cb, cn, K_CODES);
    rownorm256_kernel<<<B_ROWS * 32 / 256, 256>>>(z,  zn, B_ROWS);

    // S = z @ codebook^T
    sgemm_kernel<false, true, false><<<dim3(K_CODES/128, B_ROWS/128), blk>>>(z, cb, nullptr, S, B_ROWS, K_CODES, D_CODE);

    // argmin + gather + straight-through + row loss
    argmin_quant_kernel<<<B_ROWS, 256>>>(S, z, cb, cn, zn, qst, idxp, rl);
    loss_final_kernel<<<1, 1024>>>(rl, lossp);

    // decoder (reads quantized_st from d_out)
    sgemm_kernel<true,  false, true><<<dim3(H2DIM/128, B_ROWS/128), blk>>>(qst, dW1, db1, h2, B_ROWS, H2DIM, D_CODE);
    sgemm_kernel<true,  false, true><<<dim3(H1DIM/128, B_ROWS/128), blk>>>(h2,  dW2, db2, h1, B_ROWS, H1DIM, H2DIM);
    sgemm_kernel<false, false, true><<<dim3(D_IN/128,  B_ROWS/128), blk>>>(h1,  dW3, db3, recon, B_ROWS, D_IN, H1DIM);
}

// round 6
// speedup vs baseline: 1.3655x; 1.3655x over previous
#include <cuda_runtime.h>
#include <cuda_bf16.h>
#include <cstdint>

// ---------------- problem dims ----------------
#define B_ROWS 16384
#define D_IN   1024
#define H1DIM  2048
#define H2DIM  1024
#define D_CODE 256
#define K_CODES 1024

// output layout (f32, concatenated): recon | quantized_st | loss | indices
#define QST_OFF     (16777216)
#define LOSS_OFF    (16777216 + 4194304)                // 20971520
#define IDX_OFF     (20971521)

// ---------------- scratch (device globals; no allocation allowed) ----------------
__device__ float g_h1[B_ROWS * H1DIM];    // 128 MB (encoder h1)
__device__ float g_h2[B_ROWS * H2DIM];    // 64 MB  (encoder h2)
__device__ float g_z [B_ROWS * D_CODE];   // 16 MB
__device__ float g_S [B_ROWS * K_CODES];  // 64 MB  (z @ codebook^T)
__device__ float g_cnorm[K_CODES];
__device__ float g_znorm[B_ROWS];
__device__ float g_rowloss[B_ROWS];
// split-bf16 decoder path (hi/lo pairs)
__device__ __nv_bfloat16 g_qh [B_ROWS * D_CODE];
__device__ __nv_bfloat16 g_ql [B_ROWS * D_CODE];
__device__ __nv_bfloat16 g_a1h[B_ROWS * H2DIM];   // dec hidden 1 (1024-wide)
__device__ __nv_bfloat16 g_a1l[B_ROWS * H2DIM];
__device__ __nv_bfloat16 g_a2h[B_ROWS * H1DIM];   // dec hidden 2 (2048-wide)
__device__ __nv_bfloat16 g_a2l[B_ROWS * H1DIM];
__device__ __nv_bfloat16 g_w1h[D_CODE * H2DIM];
__device__ __nv_bfloat16 g_w1l[D_CODE * H2DIM];
__device__ __nv_bfloat16 g_w2h[H2DIM * H1DIM];
__device__ __nv_bfloat16 g_w2l[H2DIM * H1DIM];
__device__ __nv_bfloat16 g_w3h[H1DIM * D_IN];
__device__ __nv_bfloat16 g_w3l[H1DIM * D_IN];

// ---------------- helpers ----------------
static __device__ __forceinline__ uint32_t smem_u32(const void* p) {
    return (uint32_t)__cvta_generic_to_shared(p);
}
static __device__ __forceinline__ void cp16(uint32_t dst, const void* src) {
    asm volatile("cp.async.cg.shared.global [%0], [%1], 16;\n" :: "r"(dst), "l"(src));
}
static __device__ __forceinline__ void cp_commit() {
    asm volatile("cp.async.commit_group;\n");
}
template<int N> static __device__ __forceinline__ void cp_wait() {
    asm volatile("cp.async.wait_group %0;\n" :: "n"(N));
}
static __device__ __forceinline__ void ldm_x4(uint32_t& r0, uint32_t& r1, uint32_t& r2, uint32_t& r3, uint32_t a) {
    asm volatile("ldmatrix.sync.aligned.m8n8.x4.shared.b16 {%0,%1,%2,%3}, [%4];"
                 : "=r"(r0), "=r"(r1), "=r"(r2), "=r"(r3) : "r"(a));
}
static __device__ __forceinline__ void ldm_x4_t(uint32_t& r0, uint32_t& r1, uint32_t& r2, uint32_t& r3, uint32_t a) {
    asm volatile("ldmatrix.sync.aligned.m8n8.x4.trans.shared.b16 {%0,%1,%2,%3}, [%4];"
                 : "=r"(r0), "=r"(r1), "=r"(r2), "=r"(r3) : "r"(a));
}
static __device__ __forceinline__ void mma16816(float& c0, float& c1, float& c2, float& c3,
                                                uint32_t a0, uint32_t a1, uint32_t a2, uint32_t a3,
                                                uint32_t b0, uint32_t b1) {
    asm volatile("mma.sync.aligned.m16n8k16.row.col.f32.bf16.bf16.f32 "
                 "{%0,%1,%2,%3}, {%4,%5,%6,%7}, {%8,%9}, {%0,%1,%2,%3};"
                 : "+f"(c0), "+f"(c1), "+f"(c2), "+f"(c3)
                 : "r"(a0), "r"(a1), "r"(a2), "r"(a3), "r"(b0), "r"(b1));
}

// ---------------- fp32 SGEMM (encoder + distance path; byte-identical to passing R2) ----------------
template<bool RELU, bool TRANSB, bool BIAS>
__global__ __launch_bounds__(256, 2)
void sgemm_kernel(const float* __restrict__ A, const float* __restrict__ Bm,
                  const float* __restrict__ bias, float* __restrict__ C,
                  int M, int N, int K)
{
    const int BM = 128, BN = 128, BK = 16;
    __shared__ float As[BK][BM + 4];
    __shared__ float Bs[BK][BN + 4];

    const int bm = blockIdx.y * BM;
    const int bn = blockIdx.x * BN;
    const int tid = threadIdx.x;

    const int tr = (tid / 16) * 8;
    const int tc = (tid % 16) * 8;

    float acc[8][8];
#pragma unroll
    for (int i = 0; i < 8; i++)
#pragma unroll
        for (int j = 0; j < 8; j++) acc[i][j] = 0.0f;

    const int arow = tid >> 2;
    const int acol = (tid & 3) * 4;
    const int brow = tid >> 5;
    const int bcol = (tid & 31) * 4;
    const int trow = tid >> 2;
    const int tcol = (tid & 3) * 4;

    for (int k0 = 0; k0 < K; k0 += BK) {
#pragma unroll
        for (int s = 0; s < 2; s++) {
            const int r = arow + s * 64;
            float4 v = *(const float4*)&A[(long long)(bm + r) * K + k0 + acol];
            As[acol + 0][r] = v.x;
            As[acol + 1][r] = v.y;
            As[acol + 2][r] = v.z;
            As[acol + 3][r] = v.w;
        }
        if (!TRANSB) {
#pragma unroll
            for (int s = 0; s < 2; s++) {
                const int r = brow + s * 8;
                float4 v = *(const float4*)&Bm[(long long)(k0 + r) * N + bn + bcol];
                *(float4*)&Bs[r][bcol] = v;
            }
        } else {
#pragma unroll
            for (int s = 0; s < 2; s++) {
                const int n = trow + s * 64;
                float4 v = *(const float4*)&Bm[(long long)(bn + n) * K + k0 + tcol];
                Bs[tcol + 0][n] = v.x;
                Bs[tcol + 1][n] = v.y;
                Bs[tcol + 2][n] = v.z;
                Bs[tcol + 3][n] = v.w;
            }
        }
        __syncthreads();

#pragma unroll
        for (int kk = 0; kk < BK; kk++) {
            float ra[8], rb[8];
#pragma unroll
            for (int i = 0; i < 8; i++) ra[i] = As[kk][tr + i];
#pragma unroll
            for (int j = 0; j < 8; j++) rb[j] = Bs[kk][tc + j];
#pragma unroll
            for (int i = 0; i < 8; i++)
#pragma unroll
                for (int j = 0; j < 8; j++)
                    acc[i][j] = fmaf(ra[i], rb[j], acc[i][j]);
        }
        __syncthreads();
    }

#pragma unroll
    for (int i = 0; i < 8; i++) {
        const long long row = bm + tr + i;
#pragma unroll
        for (int j = 0; j < 8; j += 4) {
            float4 v;
            v.x = acc[i][j + 0];
            v.y = acc[i][j + 1];
            v.z = acc[i][j + 2];
            v.w = acc[i][j + 3];
            if (BIAS) {
                const int c = bn + tc + j;
                v.x += bias[c + 0];
                v.y += bias[c + 1];
                v.z += bias[c + 2];
                v.w += bias[c + 3];
            }
            if (RELU) {
                v.x = fmaxf(v.x, 0.0f);
                v.y = fmaxf(v.y, 0.0f);
                v.z = fmaxf(v.z, 0.0f);
                v.w = fmaxf(v.w, 0.0f);
            }
            *(float4*)&C[row * N + bn + tc + j] = v;
        }
    }
}

// ---------------- split-bf16 (3-product) tensor-core GEMM: near-fp32 precision ----------------
// C = act( (Ah+Al) @ (Bh+Bl) + bias ), dropping Al*Bl (<=2^-16 relative).
// A [M,K] row-major hi/lo, B [K,N] row-major hi/lo.
// OUT_SPLIT: write hi/lo bf16 pair; else write fp32.
template<bool RELU, bool OUT_SPLIT>
__global__ __launch_bounds__(256, 2)
void bgemm3_kernel(const __nv_bfloat16* __restrict__ Ah, const __nv_bfloat16* __restrict__ Al,
                   const __nv_bfloat16* __restrict__ Bh, const __nv_bfloat16* __restrict__ Bl,
                   const float* __restrict__ bias,
                   __nv_bfloat16* __restrict__ Ch, __nv_bfloat16* __restrict__ Cl,
                   float* __restrict__ Cf,
                   int M, int N, int K)
{
    const int BM = 128, BN = 128, BK = 32;
    __shared__ __nv_bfloat16 sAh[BM][BK + 8];
    __shared__ __nv_bfloat16 sAl[BM][BK + 8];
    __shared__ __nv_bfloat16 sBh[BK][BN + 8];
    __shared__ __nv_bfloat16 sBl[BK][BN + 8];

    const int bm = blockIdx.y * BM;
    const int bn = blockIdx.x * BN;
    const int tid = threadIdx.x;
    const int lane = tid & 31;
    const int wid = tid >> 5;
    const int wm = (wid >> 2) * 64;   // 2 warps in m
    const int wn = (wid & 3) * 32;    // 4 warps in n

    float acc[4][4][4];
#pragma unroll
    for (int i = 0; i < 4; i++)
#pragma unroll
        for (int j = 0; j < 4; j++)
#pragma unroll
            for (int q = 0; q < 4; q++) acc[i][j][q] = 0.0f;

    const int nkt = K / BK;

    for (int kt = 0; kt < nkt; kt++) {
        const int k0 = kt * BK;
        // load 4 tiles via cp.async
#pragma unroll
        for (int s = 0; s < 2; s++) {
            const int id = tid + s * 256;
            const int r = id >> 2, c8 = (id & 3) * 8;
            cp16(smem_u32(&sAh[r][c8]), Ah + (size_t)(bm + r) * K + k0 + c8);
            cp16(smem_u32(&sAl[r][c8]), Al + (size_t)(bm + r) * K + k0 + c8);
        }
#pragma unroll
        for (int s = 0; s < 2; s++) {
            const int id = tid + s * 256;
            const int r = id >> 4, c8 = (id & 15) * 8;
            cp16(smem_u32(&sBh[r][c8]), Bh + (size_t)(k0 + r) * N + bn + c8);
            cp16(smem_u32(&sBl[r][c8]), Bl + (size_t)(k0 + r) * N + bn + c8);
        }
        cp_commit();
        cp_wait<0>();
        __syncthreads();

#pragma unroll
        for (int kk = 0; kk < BK; kk += 16) {
            uint32_t bhf[2][4], blf[2][4];
#pragma unroll
            for (int p = 0; p < 2; p++) {
                const int row = kk + (lane & 7) + (((lane >> 3) & 1) << 3);
                const int col = wn + p * 16 + ((lane >> 4) << 3);
                ldm_x4_t(bhf[p][0], bhf[p][1], bhf[p][2], bhf[p][3], smem_u32(&sBh[row][col]));
                ldm_x4_t(blf[p][0], blf[p][1], blf[p][2], blf[p][3], smem_u32(&sBl[row][col]));
            }
#pragma unroll
            for (int mi = 0; mi < 4; mi++) {
                const int row = wm + mi * 16 + (lane & 15);
                const int col = kk + ((lane >> 4) << 3);
                uint32_t ahf[4], alf[4];
                ldm_x4(ahf[0], ahf[1], ahf[2], ahf[3], smem_u32(&sAh[row][col]));
                ldm_x4(alf[0], alf[1], alf[2], alf[3], smem_u32(&sAl[row][col]));
#pragma unroll
                for (int ni = 0; ni < 4; ni++) {
                    uint32_t b0h = bhf[ni >> 1][(ni & 1) * 2], b1h = bhf[ni >> 1][(ni & 1) * 2 + 1];
                    uint32_t b0l = blf[ni >> 1][(ni & 1) * 2], b1l = blf[ni >> 1][(ni & 1) * 2 + 1];
                    // hi*hi
                    mma16816(acc[mi][ni][0], acc[mi][ni][1], acc[mi][ni][2], acc[mi][ni][3],
                             ahf[0], ahf[1], ahf[2], ahf[3], b0h, b1h);
                    // hi*lo
                    mma16816(acc[mi][ni][0], acc[mi][ni][1], acc[mi][ni][2], acc[mi][ni][3],
                             ahf[0], ahf[1], ahf[2], ahf[3], b0l, b1l);
                    // lo*hi
                    mma16816(acc[mi][ni][0], acc[mi][ni][1], acc[mi][ni][2], acc[mi][ni][3],
                             alf[0], alf[1], alf[2], alf[3], b0h, b1h);
                }
            }
        }
        __syncthreads();
    }

    // epilogue
#pragma unroll
    for (int mi = 0; mi < 4; mi++) {
#pragma unroll
        for (int ni = 0; ni < 4; ni++) {
            const int col = bn + wn + ni * 8 + (lane & 3) * 2;
            const float b0 = bias[col + 0];
            const float b1 = bias[col + 1];
            const long long r0 = bm + wm + mi * 16 + (lane >> 2);
            const long long r1 = r0 + 8;
            float v00 = acc[mi][ni][0] + b0;
            float v01 = acc[mi][ni][1] + b1;
            float v10 = acc[mi][ni][2] + b0;
            float v11 = acc[mi][ni][3] + b1;
            if (RELU) {
                v00 = fmaxf(v00, 0.0f); v01 = fmaxf(v01, 0.0f);
                v10 = fmaxf(v10, 0.0f); v11 = fmaxf(v11, 0.0f);
            }
            if (OUT_SPLIT) {
                __nv_bfloat162 h0 = __floats2bfloat162_rn(v00, v01);
                __nv_bfloat162 h1 = __floats2bfloat162_rn(v10, v11);
                __nv_bfloat162 l0 = __floats2bfloat162_rn(v00 - __bfloat162float(h0.x),
                                                          v01 - __bfloat162float(h0.y));
                __nv_bfloat162 l1 = __floats2bfloat162_rn(v10 - __bfloat162float(h1.x),
                                                          v11 - __bfloat162float(h1.y));
                *(__nv_bfloat162*)&Ch[r0 * N + col] = h0;
                *(__nv_bfloat162*)&Ch[r1 * N + col] = h1;
                *(__nv_bfloat162*)&Cl[r0 * N + col] = l0;
                *(__nv_bfloat162*)&Cl[r1 * N + col] = l1;
            } else {
                *(float2*)&Cf[r0 * N + col] = make_float2(v00, v01);
                *(float2*)&Cf[r1 * N + col] = make_float2(v10, v11);
            }
        }
    }
}

// ---------------- fp32 -> split bf16 conversion ----------------
__global__ void f2bf_split_kernel(const float* __restrict__ in,
                                  __nv_bfloat16* __restrict__ oh,
                                  __nv_bfloat16* __restrict__ ol, int n4)
{
    const int i = blockIdx.x * blockDim.x + threadIdx.x;
    if (i < n4) {
        float4 v = *(const float4*)&in[i * 4];
        __nv_bfloat162 h0 = __floats2bfloat162_rn(v.x, v.y);
        __nv_bfloat162 h1 = __floats2bfloat162_rn(v.z, v.w);
        __nv_bfloat162 l0 = __floats2bfloat162_rn(v.x - __bfloat162float(h0.x),
                                                  v.y - __bfloat162float(h0.y));
        __nv_bfloat162 l1 = __floats2bfloat162_rn(v.z - __bfloat162float(h1.x),
                                                  v.w - __bfloat162float(h1.y));
        *(__nv_bfloat162*)&oh[i * 4 + 0] = h0;
        *(__nv_bfloat162*)&oh[i * 4 + 2] = h1;
        *(__nv_bfloat162*)&ol[i * 4 + 0] = l0;
        *(__nv_bfloat162*)&ol[i * 4 + 2] = l1;
    }
}

// ---------------- row squared-norms (256-wide rows, warp per row) ----------------
__global__ void rownorm256_kernel(const float* __restrict__ X, float* __restrict__ out,
                                  int rows)
{
    const int gw = (blockIdx.x * blockDim.x + threadIdx.x) >> 5;
    const int lane = threadIdx.x & 31;
    if (gw >= rows) return;
    const float* r = X + (long long)gw * 256;
    float a = 0.0f;
#pragma unroll
    for (int i = 0; i < 8; i++) {
        float v = r[lane + i * 32];
        a = fmaf(v, v, a);
    }
#pragma unroll
    for (int o = 16; o > 0; o >>= 1) a += __shfl_xor_sync(0xffffffffu, a, o);
    if (lane == 0) out[gw] = a;
}

// ---------------- argmin + gather + straight-through + row loss ----------------
__global__ void argmin_quant_kernel(const float* __restrict__ S,
                                    const float* __restrict__ z,
                                    const float* __restrict__ codebook,
                                    const float* __restrict__ cnorm,
                                    const float* __restrict__ znorm,
                                    float* __restrict__ out_qst,
                                    __nv_bfloat16* __restrict__ out_qh,
                                    __nv_bfloat16* __restrict__ out_ql,
                                    float* __restrict__ out_idx,
                                    float* __restrict__ rowloss)
{
    const int b = blockIdx.x;
    const int tid = threadIdx.x;   // 256 threads
    const float zn = znorm[b];

    float bestv = __int_as_float(0x7f800000);
    int besti = 0x7fffffff;
#pragma unroll
    for (int s = 0; s < K_CODES / 256; s++) {
        const int k = tid + s * 256;
        const float t = zn + cnorm[k];
        const float score = t - 2.0f * S[(long long)b * K_CODES + k];
        if (score < bestv) { bestv = score; besti = k; }
    }

    __shared__ float sv[256];
    __shared__ int   si[256];
    sv[tid] = bestv; si[tid] = besti;
    __syncthreads();
#pragma unroll
    for (int s = 128; s > 0; s >>= 1) {
        if (tid < s) {
            const float v2 = sv[tid + s];
            const int   i2 = si[tid + s];
            if (v2 < sv[tid] || (v2 == sv[tid] && i2 < si[tid])) {
                sv[tid] = v2; si[tid] = i2;
            }
        }
        __syncthreads();
    }
    const int idx = si[0];
    if (tid == 0) out_idx[b] = (float)idx;

    const float q = codebook[(long long)idx * D_CODE + tid];
    const float zv = z[(long long)b * D_CODE + tid];
    const float d = q - zv;
    const float qstv = zv + d;
    out_qst[(long long)b * D_CODE + tid] = qstv;
    const __nv_bfloat16 h = __float2bfloat16(qstv);
    out_qh[(long long)b * D_CODE + tid] = h;
    out_ql[(long long)b * D_CODE + tid] = __float2bfloat16(qstv - __bfloat162float(h));
    __syncthreads();
    sv[tid] = d * d;
    __syncthreads();
#pragma unroll
    for (int s = 128; s > 0; s >>= 1) {
        if (tid < s) sv[tid] += sv[tid + s];
        __syncthreads();
    }
    if (tid == 0) rowloss[b] = sv[0];
}

__global__ void loss_final_kernel(const float* __restrict__ rowloss,
                                  float* __restrict__ out_loss)
{
    __shared__ float s[1024];
    const int tid = threadIdx.x;
    float a = 0.0f;
    for (int i = tid; i < B_ROWS; i += 1024) a += rowloss[i];
    s[tid] = a;
    __syncthreads();
#pragma unroll
    for (int t = 512; t > 0; t >>= 1) {
        if (tid < t) s[tid] += s[tid + t];
        __syncthreads();
    }
    if (tid == 0) *out_loss = s[0] * (1.25f / (float)(B_ROWS * D_CODE));
}

// ---------------- launch ----------------
template<typename T>
static inline T* sym(const void* s) {
    void* p = nullptr;
    cudaGetSymbolAddress(&p, s);
    return (T*)p;
}

extern "C" void kernel_launch(void* const* d_in, const int* in_sizes, int n_in,
                              void* d_out, int out_size)
{
    const float* x    = (const float*)d_in[0];
    const float* eW1  = (const float*)d_in[1];
    const float* eb1  = (const float*)d_in[2];
    const float* eW2  = (const float*)d_in[3];
    const float* eb2  = (const float*)d_in[4];
    const float* eW3  = (const float*)d_in[5];
    const float* eb3  = (const float*)d_in[6];
    const float* cb   = (const float*)d_in[7];
    const float* dW1  = (const float*)d_in[8];
    const float* db1  = (const float*)d_in[9];
    const float* dW2  = (const float*)d_in[10];
    const float* db2  = (const float*)d_in[11];
    const float* dW3  = (const float*)d_in[12];
    const float* db3  = (const float*)d_in[13];

    float* out   = (float*)d_out;
    float* recon = out;
    float* qst   = out + QST_OFF;
    float* lossp = out + LOSS_OFF;
    float* idxp  = out + IDX_OFF;

    float* h1 = sym<float>(g_h1);
    float* h2 = sym<float>(g_h2);
    float* z  = sym<float>(g_z);
    float* S  = sym<float>(g_S);
    float* cn = sym<float>(g_cnorm);
    float* zn = sym<float>(g_znorm);
    float* rl = sym<float>(g_rowloss);
    __nv_bfloat16* qh  = sym<__nv_bfloat16>(g_qh);
    __nv_bfloat16* ql  = sym<__nv_bfloat16>(g_ql);
    __nv_bfloat16* a1h = sym<__nv_bfloat16>(g_a1h);
    __nv_bfloat16* a1l = sym<__nv_bfloat16>(g_a1l);
    __nv_bfloat16* a2h = sym<__nv_bfloat16>(g_a2h);
    __nv_bfloat16* a2l = sym<__nv_bfloat16>(g_a2l);
    __nv_bfloat16* w1h = sym<__nv_bfloat16>(g_w1h);
    __nv_bfloat16* w1l = sym<__nv_bfloat16>(g_w1l);
    __nv_bfloat16* w2h = sym<__nv_bfloat16>(g_w2h);
    __nv_bfloat16* w2l = sym<__nv_bfloat16>(g_w2l);
    __nv_bfloat16* w3h = sym<__nv_bfloat16>(g_w3h);
    __nv_bfloat16* w3l = sym<__nv_bfloat16>(g_w3l);

    dim3 blk(256);

    // decoder weight split conversions (independent; overlap with encoder)
    f2bf_split_kernel<<<(D_CODE * H2DIM / 4 + 255) / 256, 256>>>(dW1, w1h, w1l, D_CODE * H2DIM / 4);
    f2bf_split_kernel<<<(H2DIM * H1DIM / 4 + 255) / 256, 256>>>(dW2, w2h, w2l, H2DIM * H1DIM / 4);
    f2bf_split_kernel<<<(H1DIM * D_IN  / 4 + 255) / 256, 256>>>(dW3, w3h, w3l, H1DIM * D_IN / 4);

    // encoder (fp32-exact: feeds argmin)
    sgemm_kernel<true,  false, true><<<dim3(H1DIM/128, B_ROWS/128), blk>>>(x,  eW1, eb1, h1, B_ROWS, H1DIM, D_IN);
    sgemm_kernel<true,  false, true><<<dim3(H2DIM/128, B_ROWS/128), blk>>>(h1, eW2, eb2, h2, B_ROWS, H2DIM, H1DIM);
    sgemm_kernel<false, false, true><<<dim3(D_CODE/128, B_ROWS/128), blk>>>(h2, eW3, eb3, z, B_ROWS, D_CODE, H2DIM);

    // norms
    rownorm256_kernel<<<K_CODES * 32 / 256, 256>>>(cb, cn, K_CODES);
    rownorm256_kernel<<<B_ROWS * 32 / 256, 256>>>(z,  zn, B_ROWS);

    // S = z @ codebook^T (fp32-exact)
    sgemm_kernel<false, true, false><<<dim3(K_CODES/128, B_ROWS/128), blk>>>(z, cb, nullptr, S, B_ROWS, K_CODES, D_CODE);

    // argmin + gather + straight-through + row loss (+ split-bf16 copy of qst)
    argmin_quant_kernel<<<B_ROWS, 256>>>(S, z, cb, cn, zn, qst, qh, ql, idxp, rl);
    loss_final_kernel<<<1, 1024>>>(rl, lossp);

    // decoder: split-bf16 tensor cores, ~5e-5 rel err (budget 1e-3)
    bgemm3_kernel<true,  true ><<<dim3(H2DIM/128, B_ROWS/128), blk>>>(qh, ql, w1h, w1l, db1, a1h, a1l, nullptr, B_ROWS, H2DIM, D_CODE);
    bgemm3_kernel<true,  true ><<<dim3(H1DIM/128, B_ROWS/128), blk>>>(a1h, a1l, w2h, w2l, db2, a2h, a2l, nullptr, B_ROWS, H1DIM, H2DIM);
    bgemm3_kernel<false, false><<<dim3(D_IN /128, B_ROWS/128), blk>>>(a2h, a2l, w3h, w3l, db3, nullptr, nullptr, recon, B_ROWS, D_IN, H1DIM);
}

// round 9
// speedup vs baseline: 1.9034x; 1.3939x over previous
#include <cuda_runtime.h>
#include <cuda_bf16.h>
#include <cstdint>

// ---------------- problem dims ----------------
#define B_ROWS 16384
#define D_IN   1024
#define H1DIM  2048
#define H2DIM  1024
#define D_CODE 256
#define K_CODES 1024

// output layout (f32, concatenated): recon | quantized_st | loss | indices
#define QST_OFF     (16777216)
#define LOSS_OFF    (16777216 + 4194304)                // 20971520
#define IDX_OFF     (20971521)

// ---------------- scratch (device globals; no allocation allowed) ----------------
__device__ float g_z [B_ROWS * D_CODE];   // 16 MB
__device__ float g_S [B_ROWS * K_CODES];  // 64 MB  (z @ codebook^T)
__device__ float g_cnorm[K_CODES];
__device__ float g_znorm[B_ROWS];
__device__ float g_rowloss[B_ROWS];

// encoder split-3 bf16 path (hi/mid/lo; ~2^-24 combined precision)
__device__ __nv_bfloat16 g_x3 [3][B_ROWS * D_IN];
__device__ __nv_bfloat16 g_h13[3][B_ROWS * H1DIM];
__device__ __nv_bfloat16 g_h23[3][B_ROWS * H2DIM];
__device__ __nv_bfloat16 g_e1w[3][D_IN  * H1DIM];
__device__ __nv_bfloat16 g_e2w[3][H1DIM * H2DIM];
__device__ __nv_bfloat16 g_e3w[3][H2DIM * D_CODE];

// decoder split-2 bf16 path (hi/lo; ~2^-16)
__device__ __nv_bfloat16 g_q2 [2][B_ROWS * D_CODE];
__device__ __nv_bfloat16 g_a12[2][B_ROWS * H2DIM];
__device__ __nv_bfloat16 g_a22[2][B_ROWS * H1DIM];
__device__ __nv_bfloat16 g_d1w[2][D_CODE * H2DIM];
__device__ __nv_bfloat16 g_d2w[2][H2DIM * H1DIM];
__device__ __nv_bfloat16 g_d3w[2][H1DIM * D_IN];

// ---------------- helpers ----------------
static __device__ __forceinline__ uint32_t smem_u32(const void* p) {
    return (uint32_t)__cvta_generic_to_shared(p);
}
static __device__ __forceinline__ void cp16(uint32_t dst, const void* src) {
    asm volatile("cp.async.cg.shared.global [%0], [%1], 16;\n" :: "r"(dst), "l"(src));
}
static __device__ __forceinline__ void cp_commit() {
    asm volatile("cp.async.commit_group;\n");
}
template<int N> static __device__ __forceinline__ void cp_wait() {
    asm volatile("cp.async.wait_group %0;\n" :: "n"(N));
}
static __device__ __forceinline__ void ldm_x4(uint32_t& r0, uint32_t& r1, uint32_t& r2, uint32_t& r3, uint32_t a) {
    asm volatile("ldmatrix.sync.aligned.m8n8.x4.shared.b16 {%0,%1,%2,%3}, [%4];"
                 : "=r"(r0), "=r"(r1), "=r"(r2), "=r"(r3) : "r"(a));
}
static __device__ __forceinline__ void ldm_x4_t(uint32_t& r0, uint32_t& r1, uint32_t& r2, uint32_t& r3, uint32_t a) {
    asm volatile("ldmatrix.sync.aligned.m8n8.x4.trans.shared.b16 {%0,%1,%2,%3}, [%4];"
                 : "=r"(r0), "=r"(r1), "=r"(r2), "=r"(r3) : "r"(a));
}
static __device__ __forceinline__ void mma16816(float& c0, float& c1, float& c2, float& c3,
                                                uint32_t a0, uint32_t a1, uint32_t a2, uint32_t a3,
                                                uint32_t b0, uint32_t b1) {
    asm volatile("mma.sync.aligned.m16n8k16.row.col.f32.bf16.bf16.f32 "
                 "{%0,%1,%2,%3}, {%4,%5,%6,%7}, {%8,%9}, {%0,%1,%2,%3};"
                 : "+f"(c0), "+f"(c1), "+f"(c2), "+f"(c3)
                 : "r"(a0), "r"(a1), "r"(a2), "r"(a3), "r"(b0), "r"(b1));
}

// ---------------- split-bf16 tensor-core GEMM (NS-term splits, triangular products) ----------------
// C = act( sum_{i+j<NS} A_i @ B_j + bias ).  NS=3: ~2^-24 precision; NS=2: ~2^-16.
// A [M,K] row-major splits, B [K,N] row-major splits.
// OUT_SPLIT: write NS-way split bf16; else write fp32 to Cf.
template<int NS, bool RELU, bool OUT_SPLIT>
__global__ __launch_bounds__(256, 2)
void bgemmN_kernel(const __nv_bfloat16* __restrict__ A0, const __nv_bfloat16* __restrict__ A1,
                   const __nv_bfloat16* __restrict__ A2,
                   const __nv_bfloat16* __restrict__ B0, const __nv_bfloat16* __restrict__ B1,
                   const __nv_bfloat16* __restrict__ B2,
                   const float* __restrict__ bias,
                   __nv_bfloat16* __restrict__ C0, __nv_bfloat16* __restrict__ C1,
                   __nv_bfloat16* __restrict__ C2, float* __restrict__ Cf,
                   int M, int N, int K)
{
    const int BK = 32;
    const int AT = 128 * (BK + 8);   // 5120 elems per A split tile
    const int BT = BK * (128 + 8);   // 4352 elems per B split tile
    const int STG = NS * (AT + BT);  // per-stage elems

    extern __shared__ __nv_bfloat16 dsm[];
    const uint32_t sbase = smem_u32(dsm);

    const int bm = blockIdx.y * 128;
    const int bn = blockIdx.x * 128;
    const int tid = threadIdx.x;
    const int lane = tid & 31;
    const int wid = tid >> 5;
    const int wm = (wid >> 2) * 64;   // 2 warps in m
    const int wn = (wid & 3) * 32;    // 4 warps in n

    const __nv_bfloat16* Ap[3] = {A0, A1, A2};
    const __nv_bfloat16* Bp[3] = {B0, B1, B2};

    float acc[4][4][4];
#pragma unroll
    for (int i = 0; i < 4; i++)
#pragma unroll
        for (int j = 0; j < 4; j++)
#pragma unroll
            for (int q = 0; q < 4; q++) acc[i][j][q] = 0.0f;

    auto sAaddr = [&](int st, int s) -> uint32_t { return sbase + (uint32_t)(st * STG + s * AT) * 2u; };
    auto sBaddr = [&](int st, int s) -> uint32_t { return sbase + (uint32_t)(st * STG + NS * AT + s * BT) * 2u; };

    auto load_tiles = [&](int k0, int st) {
#pragma unroll
        for (int s = 0; s < NS; s++) {
#pragma unroll
            for (int t = 0; t < 2; t++) {
                const int id = tid + t * 256;
                const int r = id >> 2, c = (id & 3) * 8;
                cp16(sAaddr(st, s) + (uint32_t)(r * (BK + 8) + c) * 2u,
                     Ap[s] + (size_t)(bm + r) * K + k0 + c);
            }
#pragma unroll
            for (int t = 0; t < 2; t++) {
                const int id = tid + t * 256;
                const int r = id >> 4, c = (id & 15) * 8;
                cp16(sBaddr(st, s) + (uint32_t)(r * (128 + 8) + c) * 2u,
                     Bp[s] + (size_t)(k0 + r) * N + bn + c);
            }
        }
        cp_commit();
    };

    const int nkt = K / BK;
    load_tiles(0, 0);

    for (int kt = 0; kt < nkt; kt++) {
        const int st = kt & 1;
        if (kt + 1 < nkt) {
            load_tiles((kt + 1) * BK, (kt + 1) & 1);
            cp_wait<1>();
        } else {
            cp_wait<0>();
        }
        __syncthreads();

#pragma unroll
        for (int kk = 0; kk < BK; kk += 16) {
            uint32_t bfr[2][NS][4];
#pragma unroll
            for (int p = 0; p < 2; p++) {
                const int row = kk + (lane & 7) + (((lane >> 3) & 1) << 3);
                const int col = wn + p * 16 + ((lane >> 4) << 3);
#pragma unroll
                for (int s = 0; s < NS; s++)
                    ldm_x4_t(bfr[p][s][0], bfr[p][s][1], bfr[p][s][2], bfr[p][s][3],
                             sBaddr(st, s) + (uint32_t)(row * (128 + 8) + col) * 2u);
            }
#pragma unroll
            for (int mi = 0; mi < 4; mi++) {
                const int row = wm + mi * 16 + (lane & 15);
                const int col = kk + ((lane >> 4) << 3);
                uint32_t afr[NS][4];
#pragma unroll
                for (int s = 0; s < NS; s++)
                    ldm_x4(afr[s][0], afr[s][1], afr[s][2], afr[s][3],
                           sAaddr(st, s) + (uint32_t)(row * (BK + 8) + col) * 2u);
#pragma unroll
                for (int ni = 0; ni < 4; ni++) {
                    const int p = ni >> 1, q = (ni & 1) * 2;
#pragma unroll
                    for (int i = 0; i < NS; i++)
#pragma unroll
                        for (int j = 0; j < NS; j++)
                            if (i + j < NS)
                                mma16816(acc[mi][ni][0], acc[mi][ni][1], acc[mi][ni][2], acc[mi][ni][3],
                                         afr[i][0], afr[i][1], afr[i][2], afr[i][3],
                                         bfr[p][j][q], bfr[p][j][q + 1]);
                }
            }
        }
        __syncthreads();
    }

    // epilogue
#pragma unroll
    for (int mi = 0; mi < 4; mi++) {
#pragma unroll
        for (int ni = 0; ni < 4; ni++) {
            const int col = bn + wn + ni * 8 + (lane & 3) * 2;
            const float b0 = bias[col + 0];
            const float b1 = bias[col + 1];
            const long long r0 = bm + wm + mi * 16 + (lane >> 2);
            const long long r1 = r0 + 8;
            float v[4];
            v[0] = acc[mi][ni][0] + b0;
            v[1] = acc[mi][ni][1] + b1;
            v[2] = acc[mi][ni][2] + b0;
            v[3] = acc[mi][ni][3] + b1;
            if (RELU) {
#pragma unroll
                for (int t = 0; t < 4; t++) v[t] = fmaxf(v[t], 0.0f);
            }
            if (OUT_SPLIT) {
                float r[4] = {v[0], v[1], v[2], v[3]};
                __nv_bfloat16* Co[3] = {C0, C1, C2};
#pragma unroll
                for (int s = 0; s < NS; s++) {
                    __nv_bfloat162 p0 = __floats2bfloat162_rn(r[0], r[1]);
                    __nv_bfloat162 p1 = __floats2bfloat162_rn(r[2], r[3]);
                    *(__nv_bfloat162*)&Co[s][r0 * N + col] = p0;
                    *(__nv_bfloat162*)&Co[s][r1 * N + col] = p1;
                    if (s + 1 < NS) {
                        r[0] -= __bfloat162float(p0.x);
                        r[1] -= __bfloat162float(p0.y);
                        r[2] -= __bfloat162float(p1.x);
                        r[3] -= __bfloat162float(p1.y);
                    }
                }
            } else {
                *(float2*)&Cf[r0 * N + col] = make_float2(v[0], v[1]);
                *(float2*)&Cf[r1 * N + col] = make_float2(v[2], v[3]);
            }
        }
    }
}

// ---------------- fp32 SGEMM TRANSB (distance GEMM only; fp32-exact) ----------------
__global__ __launch_bounds__(256, 2)
void sgemm_tb_kernel(const float* __restrict__ A, const float* __restrict__ Bm,
                     float* __restrict__ C, int M, int N, int K)
{
    const int BM = 128, BN = 128, BK = 16;
    __shared__ float As[BK][BM + 4];
    __shared__ float Bs[BK][BN + 4];

    const int bm = blockIdx.y * BM;
    const int bn = blockIdx.x * BN;
    const int tid = threadIdx.x;
    const int tr = (tid / 16) * 8;
    const int tc = (tid % 16) * 8;

    float acc[8][8];
#pragma unroll
    for (int i = 0; i < 8; i++)
#pragma unroll
        for (int j = 0; j < 8; j++) acc[i][j] = 0.0f;

    const int arow = tid >> 2;
    const int acol = (tid & 3) * 4;
    const int trow = tid >> 2;
    const int tcol = (tid & 3) * 4;

    for (int k0 = 0; k0 < K; k0 += BK) {
#pragma unroll
        for (int s = 0; s < 2; s++) {
            const int r = arow + s * 64;
            float4 v = *(const float4*)&A[(long long)(bm + r) * K + k0 + acol];
            As[acol + 0][r] = v.x;
            As[acol + 1][r] = v.y;
            As[acol + 2][r] = v.z;
            As[acol + 3][r] = v.w;
        }
#pragma unroll
        for (int s = 0; s < 2; s++) {
            const int n = trow + s * 64;
            float4 v = *(const float4*)&Bm[(long long)(bn + n) * K + k0 + tcol];
            Bs[tcol + 0][n] = v.x;
            Bs[tcol + 1][n] = v.y;
            Bs[tcol + 2][n] = v.z;
            Bs[tcol + 3][n] = v.w;
        }
        __syncthreads();

#pragma unroll
        for (int kk = 0; kk < BK; kk++) {
            float ra[8], rb[8];
#pragma unroll
            for (int i = 0; i < 8; i++) ra[i] = As[kk][tr + i];
#pragma unroll
            for (int j = 0; j < 8; j++) rb[j] = Bs[kk][tc + j];
#pragma unroll
            for (int i = 0; i < 8; i++)
#pragma unroll
                for (int j = 0; j < 8; j++)
                    acc[i][j] = fmaf(ra[i], rb[j], acc[i][j]);
        }
        __syncthreads();
    }

#pragma unroll
    for (int i = 0; i < 8; i++) {
        const long long row = bm + tr + i;
#pragma unroll
        for (int j = 0; j < 8; j += 4) {
            float4 v = make_float4(acc[i][j], acc[i][j+1], acc[i][j+2], acc[i][j+3]);
            *(float4*)&C[row * N + bn + tc + j] = v;
        }
    }
}

// ---------------- fp32 -> split conversions ----------------
__global__ void f2bf3_kernel(const float* __restrict__ in,
                             __nv_bfloat16* __restrict__ o0,
                             __nv_bfloat16* __restrict__ o1,
                             __nv_bfloat16* __restrict__ o2, int n4)
{
    const int i = blockIdx.x * blockDim.x + threadIdx.x;
    if (i >= n4) return;
    float4 v = *(const float4*)&in[i * 4];
    float r[4] = {v.x, v.y, v.z, v.w};
    __nv_bfloat16* o[3] = {o0, o1, o2};
#pragma unroll
    for (int s = 0; s < 3; s++) {
        __nv_bfloat162 p0 = __floats2bfloat162_rn(r[0], r[1]);
        __nv_bfloat162 p1 = __floats2bfloat162_rn(r[2], r[3]);
        *(__nv_bfloat162*)&o[s][i * 4 + 0] = p0;
        *(__nv_bfloat162*)&o[s][i * 4 + 2] = p1;
        if (s < 2) {
            r[0] -= __bfloat162float(p0.x);
            r[1] -= __bfloat162float(p0.y);
            r[2] -= __bfloat162float(p1.x);
            r[3] -= __bfloat162float(p1.y);
        }
    }
}

__global__ void f2bf2_kernel(const float* __restrict__ in,
                             __nv_bfloat16* __restrict__ oh,
                             __nv_bfloat16* __restrict__ ol, int n4)
{
    const int i = blockIdx.x * blockDim.x + threadIdx.x;
    if (i >= n4) return;
    float4 v = *(const float4*)&in[i * 4];
    __nv_bfloat162 h0 = __floats2bfloat162_rn(v.x, v.y);
    __nv_bfloat162 h1 = __floats2bfloat162_rn(v.z, v.w);
    __nv_bfloat162 l0 = __floats2bfloat162_rn(v.x - __bfloat162float(h0.x),
                                              v.y - __bfloat162float(h0.y));
    __nv_bfloat162 l1 = __floats2bfloat162_rn(v.z - __bfloat162float(h1.x),
                                              v.w - __bfloat162float(h1.y));
    *(__nv_bfloat162*)&oh[i * 4 + 0] = h0;
    *(__nv_bfloat162*)&oh[i * 4 + 2] = h1;
    *(__nv_bfloat162*)&ol[i * 4 + 0] = l0;
    *(__nv_bfloat162*)&ol[i * 4 + 2] = l1;
}

// ---------------- row squared-norms (256-wide rows, warp per row) ----------------
__global__ void rownorm256_kernel(const float* __restrict__ X, float* __restrict__ out,
                                  int rows)
{
    const int gw = (blockIdx.x * blockDim.x + threadIdx.x) >> 5;
    const int lane = threadIdx.x & 31;
    if (gw >= rows) return;
    const float* r = X + (long long)gw * 256;
    float a = 0.0f;
#pragma unroll
    for (int i = 0; i < 8; i++) {
        float v = r[lane + i * 32];
        a = fmaf(v, v, a);
    }
#pragma unroll
    for (int o = 16; o > 0; o >>= 1) a += __shfl_xor_sync(0xffffffffu, a, o);
    if (lane == 0) out[gw] = a;
}

// ---------------- argmin + gather + straight-through + row loss ----------------
__global__ void argmin_quant_kernel(const float* __restrict__ S,
                                    const float* __restrict__ z,
                                    const float* __restrict__ codebook,
                                    const float* __restrict__ cnorm,
                                    const float* __restrict__ znorm,
                                    float* __restrict__ out_qst,
                                    __nv_bfloat16* __restrict__ out_qh,
                                    __nv_bfloat16* __restrict__ out_ql,
                                    float* __restrict__ out_idx,
                                    float* __restrict__ rowloss)
{
    const int b = blockIdx.x;
    const int tid = threadIdx.x;   // 256 threads
    const float zn = znorm[b];

    float bestv = __int_as_float(0x7f800000);
    int besti = 0x7fffffff;
#pragma unroll
    for (int s = 0; s < K_CODES / 256; s++) {
        const int k = tid + s * 256;
        const float t = zn + cnorm[k];
        const float score = t - 2.0f * S[(long long)b * K_CODES + k];
        if (score < bestv) { bestv = score; besti = k; }
    }

    __shared__ float sv[256];
    __shared__ int   si[256];
    sv[tid] = bestv; si[tid] = besti;
    __syncthreads();
#pragma unroll
    for (int s = 128; s > 0; s >>= 1) {
        if (tid < s) {
            const float v2 = sv[tid + s];
            const int   i2 = si[tid + s];
            if (v2 < sv[tid] || (v2 == sv[tid] && i2 < si[tid])) {
                sv[tid] = v2; si[tid] = i2;
            }
        }
        __syncthreads();
    }
    const int idx = si[0];
    if (tid == 0) out_idx[b] = (float)idx;

    const float q = codebook[(long long)idx * D_CODE + tid];
    const float zv = z[(long long)b * D_CODE + tid];
    const float d = q - zv;
    const float qstv = zv + d;
    out_qst[(long long)b * D_CODE + tid] = qstv;
    const __nv_bfloat16 h = __float2bfloat16(qstv);
    out_qh[(long long)b * D_CODE + tid] = h;
    out_ql[(long long)b * D_CODE + tid] = __float2bfloat16(qstv - __bfloat162float(h));
    __syncthreads();
    sv[tid] = d * d;
    __syncthreads();
#pragma unroll
    for (int s = 128; s > 0; s >>= 1) {
        if (tid < s) sv[tid] += sv[tid + s];
        __syncthreads();
    }
    if (tid == 0) rowloss[b] = sv[0];
}

__global__ void loss_final_kernel(const float* __restrict__ rowloss,
                                  float* __restrict__ out_loss)
{
    __shared__ float s[1024];
    const int tid = threadIdx.x;
    float a = 0.0f;
    for (int i = tid; i < B_ROWS; i += 1024) a += rowloss[i];
    s[tid] = a;
    __syncthreads();
#pragma unroll
    for (int t = 512; t > 0; t >>= 1) {
        if (tid < t) s[tid] += s[tid + t];
        __syncthreads();
    }
    if (tid == 0) *out_loss = s[0] * (1.25f / (float)(B_ROWS * D_CODE));
}

// ---------------- launch ----------------
template<typename T>
static inline T* sym(const void* s) {
    void* p = nullptr;
    cudaGetSymbolAddress(&p, s);
    return (T*)p;
}

#define NS3_SMEM (3 * 37888)   // 113664 B
#define NS2_SMEM (2 * 37888)   // 75776 B

extern "C" void kernel_launch(void* const* d_in, const int* in_sizes, int n_in,
                              void* d_out, int out_size)
{
    const float* x    = (const float*)d_in[0];
    const float* eW1  = (const float*)d_in[1];
    const float* eb1  = (const float*)d_in[2];
    const float* eW2  = (const float*)d_in[3];
    const float* eb2  = (const float*)d_in[4];
    const float* eW3  = (const float*)d_in[5];
    const float* eb3  = (const float*)d_in[6];
    const float* cb   = (const float*)d_in[7];
    const float* dW1  = (const float*)d_in[8];
    const float* db1  = (const float*)d_in[9];
    const float* dW2  = (const float*)d_in[10];
    const float* db2  = (const float*)d_in[11];
    const float* dW3  = (const float*)d_in[12];
    const float* db3  = (const float*)d_in[13];

    float* out   = (float*)d_out;
    float* recon = out;
    float* qst   = out + QST_OFF;
    float* lossp = out + LOSS_OFF;
    float* idxp  = out + IDX_OFF;

    float* z  = sym<float>(g_z);
    float* S  = sym<float>(g_S);
    float* cn = sym<float>(g_cnorm);
    float* zn = sym<float>(g_znorm);
    float* rl = sym<float>(g_rowloss);

    __nv_bfloat16* x3[3], *h13[3], *h23[3], *e1w[3], *e2w[3], *e3w[3];
    __nv_bfloat16* base;
    base = sym<__nv_bfloat16>(g_x3);  for (int s = 0; s < 3; s++) x3[s]  = base + (size_t)s * B_ROWS * D_IN;
    base = sym<__nv_bfloat16>(g_h13); for (int s = 0; s < 3; s++) h13[s] = base + (size_t)s * B_ROWS * H1DIM;
    base = sym<__nv_bfloat16>(g_h23); for (int s = 0; s < 3; s++) h23[s] = base + (size_t)s * B_ROWS * H2DIM;
    base = sym<__nv_bfloat16>(g_e1w); for (int s = 0; s < 3; s++) e1w[s] = base + (size_t)s * D_IN * H1DIM;
    base = sym<__nv_bfloat16>(g_e2w); for (int s = 0; s < 3; s++) e2w[s] = base + (size_t)s * H1DIM * H2DIM;
    base = sym<__nv_bfloat16>(g_e3w); for (int s = 0; s < 3; s++) e3w[s] = base + (size_t)s * H2DIM * D_CODE;

    __nv_bfloat16* q2[2], *a12[2], *a22[2], *d1w[2], *d2w[2], *d3w[2];
    base = sym<__nv_bfloat16>(g_q2);  for (int s = 0; s < 2; s++) q2[s]  = base + (size_t)s * B_ROWS * D_CODE;
    base = sym<__nv_bfloat16>(g_a12); for (int s = 0; s < 2; s++) a12[s] = base + (size_t)s * B_ROWS * H2DIM;
    base = sym<__nv_bfloat16>(g_a22); for (int s = 0; s < 2; s++) a22[s] = base + (size_t)s * B_ROWS * H1DIM;
    base = sym<__nv_bfloat16>(g_d1w); for (int s = 0; s < 2; s++) d1w[s] = base + (size_t)s * D_CODE * H2DIM;
    base = sym<__nv_bfloat16>(g_d2w); for (int s = 0; s < 2; s++) d2w[s] = base + (size_t)s * H2DIM * H1DIM;
    base = sym<__nv_bfloat16>(g_d3w); for (int s = 0; s < 2; s++) d3w[s] = base + (size_t)s * H1DIM * D_IN;

    // dynamic smem opt-in (idempotent; host-side attribute, not a graph node)
    cudaFuncSetAttribute(bgemmN_kernel<3, true,  true >, cudaFuncAttributeMaxDynamicSharedMemorySize, NS3_SMEM);
    cudaFuncSetAttribute(bgemmN_kernel<3, false, false>, cudaFuncAttributeMaxDynamicSharedMemorySize, NS3_SMEM);
    cudaFuncSetAttribute(bgemmN_kernel<2, true,  true >, cudaFuncAttributeMaxDynamicSharedMemorySize, NS2_SMEM);
    cudaFuncSetAttribute(bgemmN_kernel<2, false, false>, cudaFuncAttributeMaxDynamicSharedMemorySize, NS2_SMEM);

    dim3 blk(256);

    // conversions: x + encoder weights (split-3), decoder weights (split-2)
    f2bf3_kernel<<<(B_ROWS * D_IN  / 4 + 255) / 256, 256>>>(x,   x3[0],  x3[1],  x3[2],  B_ROWS * D_IN / 4);
    f2bf3_kernel<<<(D_IN  * H1DIM / 4 + 255) / 256, 256>>>(eW1, e1w[0], e1w[1], e1w[2], D_IN * H1DIM / 4);
    f2bf3_kernel<<<(H1DIM * H2DIM / 4 + 255) / 256, 256>>>(eW2, e2w[0], e2w[1], e2w[2], H1DIM * H2DIM / 4);
    f2bf3_kernel<<<(H2DIM * D_CODE/ 4 + 255) / 256, 256>>>(eW3, e3w[0], e3w[1], e3w[2], H2DIM * D_CODE / 4);
    f2bf2_kernel<<<(D_CODE * H2DIM / 4 + 255) / 256, 256>>>(dW1, d1w[0], d1w[1], D_CODE * H2DIM / 4);
    f2bf2_kernel<<<(H2DIM * H1DIM / 4 + 255) / 256, 256>>>(dW2, d2w[0], d2w[1], H2DIM * H1DIM / 4);
    f2bf2_kernel<<<(H1DIM * D_IN  / 4 + 255) / 256, 256>>>(dW3, d3w[0], d3w[1], H1DIM * D_IN / 4);
    rownorm256_kernel<<<K_CODES * 32 / 256, 256>>>(cb, cn, K_CODES);

    // encoder: 6-product split-bf16 (~2^-24 precision; argmin-safe)
    bgemmN_kernel<3, true, true><<<dim3(H1DIM/128, B_ROWS/128), blk, NS3_SMEM>>>(
        x3[0], x3[1], x3[2], e1w[0], e1w[1], e1w[2], eb1,
        h13[0], h13[1], h13[2], nullptr, B_ROWS, H1DIM, D_IN);
    bgemmN_kernel<3, true, true><<<dim3(H2DIM/128, B_ROWS/128), blk, NS3_SMEM>>>(
        h13[0], h13[1], h13[2], e2w[0], e2w[1], e2w[2], eb2,
        h23[0], h23[1], h23[2], nullptr, B_ROWS, H2DIM, H1DIM);
    bgemmN_kernel<3, false, false><<<dim3(D_CODE/128, B_ROWS/128), blk, NS3_SMEM>>>(
        h23[0], h23[1], h23[2], e3w[0], e3w[1], e3w[2], eb3,
        nullptr, nullptr, nullptr, z, B_ROWS, D_CODE, H2DIM);

    // z norms + distance GEMM (fp32-exact)
    rownorm256_kernel<<<B_ROWS * 32 / 256, 256>>>(z, zn, B_ROWS);
    sgemm_tb_kernel<<<dim3(K_CODES/128, B_ROWS/128), blk>>>(z, cb, S, B_ROWS, K_CODES, D_CODE);

    // argmin + gather + straight-through + row loss (+ split-2 copy of qst)
    argmin_quant_kernel<<<B_ROWS, 256>>>(S, z, cb, cn, zn, qst, q2[0], q2[1], idxp, rl);
    loss_final_kernel<<<1, 1024>>>(rl, lossp);

    // decoder: 3-product split-bf16 (~2^-16; budget 1e-3)
    bgemmN_kernel<2, true, true><<<dim3(H2DIM/128, B_ROWS/128), blk, NS2_SMEM>>>(
        q2[0], q2[1], nullptr, d1w[0], d1w[1], nullptr, db1,
        a12[0], a12[1], nullptr, nullptr, B_ROWS, H2DIM, D_CODE);
    bgemmN_kernel<2, true, true><<<dim3(H1DIM/128, B_ROWS/128), blk, NS2_SMEM>>>(
        a12[0], a12[1], nullptr, d2w[0], d2w[1], nullptr, db2,
        a22[0], a22[1], nullptr, nullptr, B_ROWS, H1DIM, H2DIM);
    bgemmN_kernel<2, false, false><<<dim3(D_IN/128, B_ROWS/128), blk, NS2_SMEM>>>(
        a22[0], a22[1], nullptr, d3w[0], d3w[1], nullptr, db3,
        nullptr, nullptr, nullptr, recon, B_ROWS, D_IN, H1DIM);
}

// round 14
// speedup vs baseline: 2.5690x; 1.3497x over previous
#include <cuda_runtime.h>
#include <cuda_fp16.h>
#include <cstdint>

// ---------------- problem dims ----------------
#define B_ROWS 16384
#define D_IN   1024
#define H1DIM  2048
#define H2DIM  1024
#define D_CODE 256
#define K_CODES 1024

// output layout (f32, concatenated): recon | quantized_st | loss | indices
#define QST_OFF     (16777216)
#define LOSS_OFF    (16777216 + 4194304)                // 20971520
#define IDX_OFF     (20971521)

// ---------------- scratch (device globals; no allocation allowed) ----------------
__device__ float g_z [B_ROWS * D_CODE];   // 16 MB
__device__ float g_S [B_ROWS * K_CODES];  // 64 MB  (z @ codebook^T)
__device__ float g_cnorm[K_CODES];
__device__ float g_znorm[B_ROWS];
__device__ float g_rowloss[B_ROWS];

// split-2 fp16 operands (hi/lo; 3-product GEMM => ~2^-22 relative precision)
__device__ __half g_x2 [2][B_ROWS * D_IN];
__device__ __half g_h12[2][B_ROWS * H1DIM];
__device__ __half g_h22[2][B_ROWS * H2DIM];
__device__ __half g_e1w[2][D_IN  * H1DIM];
__device__ __half g_e2w[2][H1DIM * H2DIM];
__device__ __half g_e3w[2][H2DIM * D_CODE];

__device__ __half g_q2 [2][B_ROWS * D_CODE];
__device__ __half g_a12[2][B_ROWS * H2DIM];
__device__ __half g_a22[2][B_ROWS * H1DIM];
__device__ __half g_d1w[2][D_CODE * H2DIM];
__device__ __half g_d2w[2][H2DIM * H1DIM];
__device__ __half g_d3w[2][H1DIM * D_IN];

// ---------------- helpers ----------------
static __device__ __forceinline__ uint32_t smem_u32(const void* p) {
    return (uint32_t)__cvta_generic_to_shared(p);
}
static __device__ __forceinline__ void cp16(uint32_t dst, const void* src) {
    asm volatile("cp.async.cg.shared.global [%0], [%1], 16;\n" :: "r"(dst), "l"(src));
}
static __device__ __forceinline__ void cp_commit() {
    asm volatile("cp.async.commit_group;\n");
}
template<int N> static __device__ __forceinline__ void cp_wait() {
    asm volatile("cp.async.wait_group %0;\n" :: "n"(N));
}
static __device__ __forceinline__ void ldm_x4(uint32_t& r0, uint32_t& r1, uint32_t& r2, uint32_t& r3, uint32_t a) {
    asm volatile("ldmatrix.sync.aligned.m8n8.x4.shared.b16 {%0,%1,%2,%3}, [%4];"
                 : "=r"(r0), "=r"(r1), "=r"(r2), "=r"(r3) : "r"(a));
}
static __device__ __forceinline__ void ldm_x4_t(uint32_t& r0, uint32_t& r1, uint32_t& r2, uint32_t& r3, uint32_t a) {
    asm volatile("ldmatrix.sync.aligned.m8n8.x4.trans.shared.b16 {%0,%1,%2,%3}, [%4];"
                 : "=r"(r0), "=r"(r1), "=r"(r2), "=r"(r3) : "r"(a));
}
static __device__ __forceinline__ void mma16816h(float& c0, float& c1, float& c2, float& c3,
                                                 uint32_t a0, uint32_t a1, uint32_t a2, uint32_t a3,
                                                 uint32_t b0, uint32_t b1) {
    asm volatile("mma.sync.aligned.m16n8k16.row.col.f32.f16.f16.f32 "
                 "{%0,%1,%2,%3}, {%4,%5,%6,%7}, {%8,%9}, {%0,%1,%2,%3};"
                 : "+f"(c0), "+f"(c1), "+f"(c2), "+f"(c3)
                 : "r"(a0), "r"(a1), "r"(a2), "r"(a3), "r"(b0), "r"(b1));
}

// ---------------- split-fp16 tensor-core GEMM (hi/lo, 3 products) ----------------
// C = act( Ah@Bh + Ah@Bl + Al@Bh + bias )  ~2^-22 relative precision.
// A [M,K] row-major splits, B [K,N] row-major splits.
// OUT_SPLIT: write hi/lo fp16 pair; else write fp32 to Cf.
template<bool RELU, bool OUT_SPLIT>
__global__ __launch_bounds__(256, 2)
void hgemm2_kernel(const __half* __restrict__ A0, const __half* __restrict__ A1,
                   const __half* __restrict__ B0, const __half* __restrict__ B1,
                   const float* __restrict__ bias,
                   __half* __restrict__ C0, __half* __restrict__ C1,
                   float* __restrict__ Cf,
                   int M, int N, int K)
{
    const int BK = 32;
    const int AT = 128 * (BK + 8);   // 5120 elems per A split tile
    const int BT = BK * (128 + 8);   // 4352 elems per B split tile
    const int STG = 2 * (AT + BT);   // per-stage elems

    extern __shared__ __half dsm[];
    const uint32_t sbase = smem_u32(dsm);

    const int bm = blockIdx.y * 128;
    const int bn = blockIdx.x * 128;
    const int tid = threadIdx.x;
    const int lane = tid & 31;
    const int wid = tid >> 5;
    const int wm = (wid >> 2) * 64;   // 2 warps in m
    const int wn = (wid & 3) * 32;    // 4 warps in n

    const __half* Ap[2] = {A0, A1};
    const __half* Bp[2] = {B0, B1};

    float acc[4][4][4];
#pragma unroll
    for (int i = 0; i < 4; i++)
#pragma unroll
        for (int j = 0; j < 4; j++)
#pragma unroll
            for (int q = 0; q < 4; q++) acc[i][j][q] = 0.0f;

    auto sAaddr = [&](int st, int s) -> uint32_t { return sbase + (uint32_t)(st * STG + s * AT) * 2u; };
    auto sBaddr = [&](int st, int s) -> uint32_t { return sbase + (uint32_t)(st * STG + 2 * AT + s * BT) * 2u; };

    auto load_tiles = [&](int k0, int st) {
#pragma unroll
        for (int s = 0; s < 2; s++) {
#pragma unroll
            for (int t = 0; t < 2; t++) {
                const int id = tid + t * 256;
                const int r = id >> 2, c = (id & 3) * 8;
                cp16(sAaddr(st, s) + (uint32_t)(r * (BK + 8) + c) * 2u,
                     Ap[s] + (size_t)(bm + r) * K + k0 + c);
            }
#pragma unroll
            for (int t = 0; t < 2; t++) {
                const int id = tid + t * 256;
                const int r = id >> 4, c = (id & 15) * 8;
                cp16(sBaddr(st, s) + (uint32_t)(r * (128 + 8) + c) * 2u,
                     Bp[s] + (size_t)(k0 + r) * N + bn + c);
            }
        }
        cp_commit();
    };

    const int nkt = K / BK;
    load_tiles(0, 0);

    for (int kt = 0; kt < nkt; kt++) {
        const int st = kt & 1;
        if (kt + 1 < nkt) {
            load_tiles((kt + 1) * BK, (kt + 1) & 1);
            cp_wait<1>();
        } else {
            cp_wait<0>();
        }
        __syncthreads();

#pragma unroll
        for (int kk = 0; kk < BK; kk += 16) {
            uint32_t bfr[2][2][4];
#pragma unroll
            for (int p = 0; p < 2; p++) {
                const int row = kk + (lane & 7) + (((lane >> 3) & 1) << 3);
                const int col = wn + p * 16 + ((lane >> 4) << 3);
#pragma unroll
                for (int s = 0; s < 2; s++)
                    ldm_x4_t(bfr[p][s][0], bfr[p][s][1], bfr[p][s][2], bfr[p][s][3],
                             sBaddr(st, s) + (uint32_t)(row * (128 + 8) + col) * 2u);
            }
#pragma unroll
            for (int mi = 0; mi < 4; mi++) {
                const int row = wm + mi * 16 + (lane & 15);
                const int col = kk + ((lane >> 4) << 3);
                uint32_t afr[2][4];
#pragma unroll
                for (int s = 0; s < 2; s++)
                    ldm_x4(afr[s][0], afr[s][1], afr[s][2], afr[s][3],
                           sAaddr(st, s) + (uint32_t)(row * (BK + 8) + col) * 2u);
#pragma unroll
                for (int ni = 0; ni < 4; ni++) {
                    const int p = ni >> 1, q = (ni & 1) * 2;
                    // hi*hi
                    mma16816h(acc[mi][ni][0], acc[mi][ni][1], acc[mi][ni][2], acc[mi][ni][3],
                              afr[0][0], afr[0][1], afr[0][2], afr[0][3],
                              bfr[p][0][q], bfr[p][0][q + 1]);
                    // hi*lo
                    mma16816h(acc[mi][ni][0], acc[mi][ni][1], acc[mi][ni][2], acc[mi][ni][3],
                              afr[0][0], afr[0][1], afr[0][2], afr[0][3],
                              bfr[p][1][q], bfr[p][1][q + 1]);
                    // lo*hi
                    mma16816h(acc[mi][ni][0], acc[mi][ni][1], acc[mi][ni][2], acc[mi][ni][3],
                              afr[1][0], afr[1][1], afr[1][2], afr[1][3],
                              bfr[p][0][q], bfr[p][0][q + 1]);
                }
            }
        }
        __syncthreads();
    }

    // epilogue
#pragma unroll
    for (int mi = 0; mi < 4; mi++) {
#pragma unroll
        for (int ni = 0; ni < 4; ni++) {
            const int col = bn + wn + ni * 8 + (lane & 3) * 2;
            const float b0 = bias[col + 0];
            const float b1 = bias[col + 1];
            const long long r0 = bm + wm + mi * 16 + (lane >> 2);
            const long long r1 = r0 + 8;
            float v[4];
            v[0] = acc[mi][ni][0] + b0;
            v[1] = acc[mi][ni][1] + b1;
            v[2] = acc[mi][ni][2] + b0;
            v[3] = acc[mi][ni][3] + b1;
            if (RELU) {
#pragma unroll
                for (int t = 0; t < 4; t++) v[t] = fmaxf(v[t], 0.0f);
            }
            if (OUT_SPLIT) {
                __half2 h0 = __floats2half2_rn(v[0], v[1]);
                __half2 h1 = __floats2half2_rn(v[2], v[3]);
                __half2 l0 = __floats2half2_rn(v[0] - __half2float(__low2half(h0)),
                                               v[1] - __half2float(__high2half(h0)));
                __half2 l1 = __floats2half2_rn(v[2] - __half2float(__low2half(h1)),
                                               v[3] - __half2float(__high2half(h1)));
                *(__half2*)&C0[r0 * N + col] = h0;
                *(__half2*)&C0[r1 * N + col] = h1;
                *(__half2*)&C1[r0 * N + col] = l0;
                *(__half2*)&C1[r1 * N + col] = l1;
            } else {
                *(float2*)&Cf[r0 * N + col] = make_float2(v[0], v[1]);
                *(float2*)&Cf[r1 * N + col] = make_float2(v[2], v[3]);
            }
        }
    }
}

// ---------------- fp32 SGEMM TRANSB (distance GEMM only; fp32-exact) ----------------
__global__ __launch_bounds__(256, 2)
void sgemm_tb_kernel(const float* __restrict__ A, const float* __restrict__ Bm,
                     float* __restrict__ C, int M, int N, int K)
{
    const int BM = 128, BN = 128, BK = 16;
    __shared__ float As[BK][BM + 4];
    __shared__ float Bs[BK][BN + 4];

    const int bm = blockIdx.y * BM;
    const int bn = blockIdx.x * BN;
    const int tid = threadIdx.x;
    const int tr = (tid / 16) * 8;
    const int tc = (tid % 16) * 8;

    float acc[8][8];
#pragma unroll
    for (int i = 0; i < 8; i++)
#pragma unroll
        for (int j = 0; j < 8; j++) acc[i][j] = 0.0f;

    const int arow = tid >> 2;
    const int acol = (tid & 3) * 4;
    const int trow = tid >> 2;
    const int tcol = (tid & 3) * 4;

    for (int k0 = 0; k0 < K; k0 += BK) {
#pragma unroll
        for (int s = 0; s < 2; s++) {
            const int r = arow + s * 64;
            float4 v = *(const float4*)&A[(long long)(bm + r) * K + k0 + acol];
            As[acol + 0][r] = v.x;
            As[acol + 1][r] = v.y;
            As[acol + 2][r] = v.z;
            As[acol + 3][r] = v.w;
        }
#pragma unroll
        for (int s = 0; s < 2; s++) {
            const int n = trow + s * 64;
            float4 v = *(const float4*)&Bm[(long long)(bn + n) * K + k0 + tcol];
            Bs[tcol + 0][n] = v.x;
            Bs[tcol + 1][n] = v.y;
            Bs[tcol + 2][n] = v.z;
            Bs[tcol + 3][n] = v.w;
        }
        __syncthreads();

#pragma unroll
        for (int kk = 0; kk < BK; kk++) {
            float ra[8], rb[8];
#pragma unroll
            for (int i = 0; i < 8; i++) ra[i] = As[kk][tr + i];
#pragma unroll
            for (int j = 0; j < 8; j++) rb[j] = Bs[kk][tc + j];
#pragma unroll
            for (int i = 0; i < 8; i++)
#pragma unroll
                for (int j = 0; j < 8; j++)
                    acc[i][j] = fmaf(ra[i], rb[j], acc[i][j]);
        }
        __syncthreads();
    }

#pragma unroll
    for (int i = 0; i < 8; i++) {
        const long long row = bm + tr + i;
#pragma unroll
        for (int j = 0; j < 8; j += 4) {
            float4 v = make_float4(acc[i][j], acc[i][j+1], acc[i][j+2], acc[i][j+3]);
            *(float4*)&C[row * N + bn + tc + j] = v;
        }
    }
}

// ---------------- fp32 -> split-fp16 conversion ----------------
__global__ void f2h2_kernel(const float* __restrict__ in,
                            __half* __restrict__ oh,
                            __half* __restrict__ ol, int n4)
{
    const int i = blockIdx.x * blockDim.x + threadIdx.x;
    if (i >= n4) return;
    float4 v = *(const float4*)&in[i * 4];
    __half2 h0 = __floats2half2_rn(v.x, v.y);
    __half2 h1 = __floats2half2_rn(v.z, v.w);
    __half2 l0 = __floats2half2_rn(v.x - __half2float(__low2half(h0)),
                                   v.y - __half2float(__high2half(h0)));
    __half2 l1 = __floats2half2_rn(v.z - __half2float(__low2half(h1)),
                                   v.w - __half2float(__high2half(h1)));
    *(__half2*)&oh[i * 4 + 0] = h0;
    *(__half2*)&oh[i * 4 + 2] = h1;
    *(__half2*)&ol[i * 4 + 0] = l0;
    *(__half2*)&ol[i * 4 + 2] = l1;
}

// ---------------- row squared-norms (256-wide rows, warp per row) ----------------
__global__ void rownorm256_kernel(const float* __restrict__ X, float* __restrict__ out,
                                  int rows)
{
    const int gw = (blockIdx.x * blockDim.x + threadIdx.x) >> 5;
    const int lane = threadIdx.x & 31;
    if (gw >= rows) return;
    const float* r = X + (long long)gw * 256;
    float a = 0.0f;
#pragma unroll
    for (int i = 0; i < 8; i++) {
        float v = r[lane + i * 32];
        a = fmaf(v, v, a);
    }
#pragma unroll
    for (int o = 16; o > 0; o >>= 1) a += __shfl_xor_sync(0xffffffffu, a, o);
    if (lane == 0) out[gw] = a;
}

// ---------------- argmin + gather + straight-through + row loss ----------------
__global__ void argmin_quant_kernel(const float* __restrict__ S,
                                    const float* __restrict__ z,
                                    const float* __restrict__ codebook,
                                    const float* __restrict__ cnorm,
                                    const float* __restrict__ znorm,
                                    float* __restrict__ out_qst,
                                    __half* __restrict__ out_qh,
                                    __half* __restrict__ out_ql,
                                    float* __restrict__ out_idx,
                                    float* __restrict__ rowloss)
{
    const int b = blockIdx.x;
    const int tid = threadIdx.x;   // 256 threads
    const float zn = znorm[b];

    float bestv = __int_as_float(0x7f800000);
    int besti = 0x7fffffff;
#pragma unroll
    for (int s = 0; s < K_CODES / 256; s++) {
        const int k = tid + s * 256;
        const float t = zn + cnorm[k];
        const float score = t - 2.0f * S[(long long)b * K_CODES + k];
        if (score < bestv) { bestv = score; besti = k; }
    }

    __shared__ float sv[256];
    __shared__ int   si[256];
    sv[tid] = bestv; si[tid] = besti;
    __syncthreads();
#pragma unroll
    for (int s = 128; s > 0; s >>= 1) {
        if (tid < s) {
            const float v2 = sv[tid + s];
            const int   i2 = si[tid + s];
            if (v2 < sv[tid] || (v2 == sv[tid] && i2 < si[tid])) {
                sv[tid] = v2; si[tid] = i2;
            }
        }
        __syncthreads();
    }
    const int idx = si[0];
    if (tid == 0) out_idx[b] = (float)idx;

    const float q = codebook[(long long)idx * D_CODE + tid];
    const float zv = z[(long long)b * D_CODE + tid];
    const float d = q - zv;
    const float qstv = zv + d;
    out_qst[(long long)b * D_CODE + tid] = qstv;
    const __half h = __float2half_rn(qstv);
    out_qh[(long long)b * D_CODE + tid] = h;
    out_ql[(long long)b * D_CODE + tid] = __float2half_rn(qstv - __half2float(h));
    __syncthreads();
    sv[tid] = d * d;
    __syncthreads();
#pragma unroll
    for (int s = 128; s > 0; s >>= 1) {
        if (tid < s) sv[tid] += sv[tid + s];
        __syncthreads();
    }
    if (tid == 0) rowloss[b] = sv[0];
}

__global__ void loss_final_kernel(const float* __restrict__ rowloss,
                                  float* __restrict__ out_loss)
{
    __shared__ float s[1024];
    const int tid = threadIdx.x;
    float a = 0.0f;
    for (int i = tid; i < B_ROWS; i += 1024) a += rowloss[i];
    s[tid] = a;
    __syncthreads();
#pragma unroll
    for (int t = 512; t > 0; t >>= 1) {
        if (tid < t) s[tid] += s[tid + t];
        __syncthreads();
    }
    if (tid == 0) *out_loss = s[0] * (1.25f / (float)(B_ROWS * D_CODE));
}

// ---------------- launch ----------------
template<typename T>
static inline T* sym(const void* s) {
    void* p = nullptr;
    cudaGetSymbolAddress(&p, s);
    return (T*)p;
}

#define NS2_SMEM (2 * 37888)   // 75776 B (2 stages x 2 splits x (A+B) tiles)

extern "C" void kernel_launch(void* const* d_in, const int* in_sizes, int n_in,
                              void* d_out, int out_size)
{
    const float* x    = (const float*)d_in[0];
    const float* eW1  = (const float*)d_in[1];
    const float* eb1  = (const float*)d_in[2];
    const float* eW2  = (const float*)d_in[3];
    const float* eb2  = (const float*)d_in[4];
    const float* eW3  = (const float*)d_in[5];
    const float* eb3  = (const float*)d_in[6];
    const float* cb   = (const float*)d_in[7];
    const float* dW1  = (const float*)d_in[8];
    const float* db1  = (const float*)d_in[9];
    const float* dW2  = (const float*)d_in[10];
    const float* db2  = (const float*)d_in[11];
    const float* dW3  = (const float*)d_in[12];
    const float* db3  = (const float*)d_in[13];

    float* out   = (float*)d_out;
    float* recon = out;
    float* qst   = out + QST_OFF;
    float* lossp = out + LOSS_OFF;
    float* idxp  = out + IDX_OFF;

    float* z  = sym<float>(g_z);
    float* S  = sym<float>(g_S);
    float* cn = sym<float>(g_cnorm);
    float* zn = sym<float>(g_znorm);
    float* rl = sym<float>(g_rowloss);

    __half *x2[2], *h12[2], *h22[2], *e1w[2], *e2w[2], *e3w[2];
    __half *q2[2], *a12[2], *a22[2], *d1w[2], *d2w[2], *d3w[2];
    __half* base;
    base = sym<__half>(g_x2);  for (int s = 0; s < 2; s++) x2[s]  = base + (size_t)s * B_ROWS * D_IN;
    base = sym<__half>(g_h12); for (int s = 0; s < 2; s++) h12[s] = base + (size_t)s * B_ROWS * H1DIM;
    base = sym<__half>(g_h22); for (int s = 0; s < 2; s++) h22[s] = base + (size_t)s * B_ROWS * H2DIM;
    base = sym<__half>(g_e1w); for (int s = 0; s < 2; s++) e1w[s] = base + (size_t)s * D_IN * H1DIM;
    base = sym<__half>(g_e2w); for (int s = 0; s < 2; s++) e2w[s] = base + (size_t)s * H1DIM * H2DIM;
    base = sym<__half>(g_e3w); for (int s = 0; s < 2; s++) e3w[s] = base + (size_t)s * H2DIM * D_CODE;
    base = sym<__half>(g_q2);  for (int s = 0; s < 2; s++) q2[s]  = base + (size_t)s * B_ROWS * D_CODE;
    base = sym<__half>(g_a12); for (int s = 0; s < 2; s++) a12[s] = base + (size_t)s * B_ROWS * H2DIM;
    base = sym<__half>(g_a22); for (int s = 0; s < 2; s++) a22[s] = base + (size_t)s * B_ROWS * H1DIM;
    base = sym<__half>(g_d1w); for (int s = 0; s < 2; s++) d1w[s] = base + (size_t)s * D_CODE * H2DIM;
    base = sym<__half>(g_d2w); for (int s = 0; s < 2; s++) d2w[s] = base + (size_t)s * H2DIM * H1DIM;
    base = sym<__half>(g_d3w); for (int s = 0; s < 2; s++) d3w[s] = base + (size_t)s * H1DIM * D_IN;

    // dynamic smem opt-in (host-side attribute, idempotent)
    cudaFuncSetAttribute(hgemm2_kernel<true,  true >, cudaFuncAttributeMaxDynamicSharedMemorySize, NS2_SMEM);
    cudaFuncSetAttribute(hgemm2_kernel<false, false>, cudaFuncAttributeMaxDynamicSharedMemorySize, NS2_SMEM);

    dim3 blk(256);

    // conversions (split-2 fp16): input + all weights
    f2h2_kernel<<<(B_ROWS * D_IN  / 4 + 255) / 256, 256>>>(x,   x2[0],  x2[1],  B_ROWS * D_IN / 4);
    f2h2_kernel<<<(D_IN  * H1DIM / 4 + 255) / 256, 256>>>(eW1, e1w[0], e1w[1], D_IN * H1DIM / 4);
    f2h2_kernel<<<(H1DIM * H2DIM / 4 + 255) / 256, 256>>>(eW2, e2w[0], e2w[1], H1DIM * H2DIM / 4);
    f2h2_kernel<<<(H2DIM * D_CODE/ 4 + 255) / 256, 256>>>(eW3, e3w[0], e3w[1], H2DIM * D_CODE / 4);
    f2h2_kernel<<<(D_CODE * H2DIM / 4 + 255) / 256, 256>>>(dW1, d1w[0], d1w[1], D_CODE * H2DIM / 4);
    f2h2_kernel<<<(H2DIM * H1DIM / 4 + 255) / 256, 256>>>(dW2, d2w[0], d2w[1], H2DIM * H1DIM / 4);
    f2h2_kernel<<<(H1DIM * D_IN  / 4 + 255) / 256, 256>>>(dW3, d3w[0], d3w[1], H1DIM * D_IN / 4);
    rownorm256_kernel<<<K_CODES * 32 / 256, 256>>>(cb, cn, K_CODES);

    // encoder: split-fp16, 3 products (~2^-22; argmin-safe)
    hgemm2_kernel<true, true><<<dim3(H1DIM/128, B_ROWS/128), blk, NS2_SMEM>>>(
        x2[0], x2[1], e1w[0], e1w[1], eb1, h12[0], h12[1], nullptr, B_ROWS, H1DIM, D_IN);
    hgemm2_kernel<true, true><<<dim3(H2DIM/128, B_ROWS/128), blk, NS2_SMEM>>>(
        h12[0], h12[1], e2w[0], e2w[1], eb2, h22[0], h22[1], nullptr, B_ROWS, H2DIM, H1DIM);
    hgemm2_kernel<false, false><<<dim3(D_CODE/128, B_ROWS/128), blk, NS2_SMEM>>>(
        h22[0], h22[1], e3w[0], e3w[1], eb3, nullptr, nullptr, z, B_ROWS, D_CODE, H2DIM);

    // z norms + distance GEMM (fp32-exact)
    rownorm256_kernel<<<B_ROWS * 32 / 256, 256>>>(z, zn, B_ROWS);
    sgemm_tb_kernel<<<dim3(K_CODES/128, B_ROWS/128), blk>>>(z, cb, S, B_ROWS, K_CODES, D_CODE);

    // argmin + gather + straight-through + row loss (+ split-2 fp16 copy of qst)
    argmin_quant_kernel<<<B_ROWS, 256>>>(S, z, cb, cn, zn, qst, q2[0], q2[1], idxp, rl);
    loss_final_kernel<<<1, 1024>>>(rl, lossp);

    // decoder: split-fp16, 3 products (~2^-22; budget 1e-3)
    hgemm2_kernel<true, true><<<dim3(H2DIM/128, B_ROWS/128), blk, NS2_SMEM>>>(
        q2[0], q2[1], d1w[0], d1w[1], db1, a12[0], a12[1], nullptr, B_ROWS, H2DIM, D_CODE);
    hgemm2_kernel<true, true><<<dim3(H1DIM/128, B_ROWS/128), blk, NS2_SMEM>>>(
        a12[0], a12[1], d2w[0], d2w[1], db2, a22[0], a22[1], nullptr, B_ROWS, H1DIM, H2DIM);
    hgemm2_kernel<false, false><<<dim3(D_IN/128, B_ROWS/128), blk, NS2_SMEM>>>(
        a22[0], a22[1], d3w[0], d3w[1], db3, nullptr, nullptr, recon, B_ROWS, D_IN, H1DIM);
}

// round 16
// speedup vs baseline: 3.4514x; 1.3435x over previous
#include <cuda_runtime.h>
#include <cuda_fp16.h>
#include <cstdint>

// ---------------- problem dims ----------------
#define B_ROWS 16384
#define D_IN   1024
#define H1DIM  2048
#define H2DIM  1024
#define D_CODE 256
#define K_CODES 1024

// output layout (f32, concatenated): recon | quantized_st | loss | indices
#define QST_OFF     (16777216)
#define LOSS_OFF    (16777216 + 4194304)                // 20971520
#define IDX_OFF     (20971521)

// ---------------- scratch (device globals; no allocation allowed) ----------------
__device__ float g_z [B_ROWS * D_CODE];   // 16 MB
__device__ float g_S [B_ROWS * K_CODES];  // 64 MB  (z @ codebook^T)
__device__ float g_cnorm[K_CODES];
__device__ float g_znorm[B_ROWS];
__device__ float g_rowloss[B_ROWS];

// encoder: split-2 fp16 (hi/lo; 3-product GEMM => ~2^-22 relative precision)
__device__ __half g_x2 [2][B_ROWS * D_IN];
__device__ __half g_h12[2][B_ROWS * H1DIM];
__device__ __half g_h22[2][B_ROWS * H2DIM];
__device__ __half g_e1w[2][D_IN  * H1DIM];
__device__ __half g_e2w[2][H1DIM * H2DIM];
__device__ __half g_e3w[2][H2DIM * D_CODE];

// decoder: single fp16 (1-product GEMM => ~2e-4 on recon; budget 1e-3)
__device__ __half g_q1 [B_ROWS * D_CODE];
__device__ __half g_a1h[B_ROWS * H2DIM];
__device__ __half g_a2h[B_ROWS * H1DIM];
__device__ __half g_d1w[D_CODE * H2DIM];
__device__ __half g_d2w[H2DIM * H1DIM];
__device__ __half g_d3w[H1DIM * D_IN];

// ---------------- helpers ----------------
static __device__ __forceinline__ uint32_t smem_u32(const void* p) {
    return (uint32_t)__cvta_generic_to_shared(p);
}
static __device__ __forceinline__ void cp16(uint32_t dst, const void* src) {
    asm volatile("cp.async.cg.shared.global [%0], [%1], 16;\n" :: "r"(dst), "l"(src));
}
static __device__ __forceinline__ void cp_commit() {
    asm volatile("cp.async.commit_group;\n");
}
template<int N> static __device__ __forceinline__ void cp_wait() {
    asm volatile("cp.async.wait_group %0;\n" :: "n"(N));
}
static __device__ __forceinline__ void ldm_x4(uint32_t& r0, uint32_t& r1, uint32_t& r2, uint32_t& r3, uint32_t a) {
    asm volatile("ldmatrix.sync.aligned.m8n8.x4.shared.b16 {%0,%1,%2,%3}, [%4];"
                 : "=r"(r0), "=r"(r1), "=r"(r2), "=r"(r3) : "r"(a));
}
static __device__ __forceinline__ void ldm_x4_t(uint32_t& r0, uint32_t& r1, uint32_t& r2, uint32_t& r3, uint32_t a) {
    asm volatile("ldmatrix.sync.aligned.m8n8.x4.trans.shared.b16 {%0,%1,%2,%3}, [%4];"
                 : "=r"(r0), "=r"(r1), "=r"(r2), "=r"(r3) : "r"(a));
}
static __device__ __forceinline__ void mma16816h(float& c0, float& c1, float& c2, float& c3,
                                                 uint32_t a0, uint32_t a1, uint32_t a2, uint32_t a3,
                                                 uint32_t b0, uint32_t b1) {
    asm volatile("mma.sync.aligned.m16n8k16.row.col.f32.f16.f16.f32 "
                 "{%0,%1,%2,%3}, {%4,%5,%6,%7}, {%8,%9}, {%0,%1,%2,%3};"
                 : "+f"(c0), "+f"(c1), "+f"(c2), "+f"(c3)
                 : "r"(a0), "r"(a1), "r"(a2), "r"(a3), "r"(b0), "r"(b1));
}

// ---------------- fp16 tensor-core GEMM ----------------
// NS=2: 3-product hi/lo split (~2^-22).  NS=1: plain fp16 (~2e-4 over 3 layers).
// A [M,K] row-major, B [K,N] row-major.
// OUTM: 0 = fp32 to Cf, 1 = split hi/lo to C0/C1, 2 = single fp16 to C0.
template<int NS, bool RELU, int OUTM>
__global__ __launch_bounds__(256, 2)
void hgemm_kernel(const __half* __restrict__ A0, const __half* __restrict__ A1,
                  const __half* __restrict__ B0, const __half* __restrict__ B1,
                  const float* __restrict__ bias,
                  __half* __restrict__ C0, __half* __restrict__ C1,
                  float* __restrict__ Cf,
                  int M, int N, int K)
{
    const int BK = 32;
    const int AT = 128 * (BK + 8);   // 5120 elems per A split tile
    const int BT = BK * (128 + 8);   // 4352 elems per B split tile
    const int STG = NS * (AT + BT);  // per-stage elems

    extern __shared__ __half dsm[];
    const uint32_t sbase = smem_u32(dsm);

    const int bm = blockIdx.y * 128;
    const int bn = blockIdx.x * 128;
    const int tid = threadIdx.x;
    const int lane = tid & 31;
    const int wid = tid >> 5;
    const int wm = (wid >> 2) * 64;   // 2 warps in m
    const int wn = (wid & 3) * 32;    // 4 warps in n

    const __half* Ap[2] = {A0, A1};
    const __half* Bp[2] = {B0, B1};

    float acc[4][4][4];
#pragma unroll
    for (int i = 0; i < 4; i++)
#pragma unroll
        for (int j = 0; j < 4; j++)
#pragma unroll
            for (int q = 0; q < 4; q++) acc[i][j][q] = 0.0f;

    auto sAaddr = [&](int st, int s) -> uint32_t { return sbase + (uint32_t)(st * STG + s * AT) * 2u; };
    auto sBaddr = [&](int st, int s) -> uint32_t { return sbase + (uint32_t)(st * STG + NS * AT + s * BT) * 2u; };

    auto load_tiles = [&](int k0, int st) {
#pragma unroll
        for (int s = 0; s < NS; s++) {
#pragma unroll
            for (int t = 0; t < 2; t++) {
                const int id = tid + t * 256;
                const int r = id >> 2, c = (id & 3) * 8;
                cp16(sAaddr(st, s) + (uint32_t)(r * (BK + 8) + c) * 2u,
                     Ap[s] + (size_t)(bm + r) * K + k0 + c);
            }
#pragma unroll
            for (int t = 0; t < 2; t++) {
                const int id = tid + t * 256;
                const int r = id >> 4, c = (id & 15) * 8;
                cp16(sBaddr(st, s) + (uint32_t)(r * (128 + 8) + c) * 2u,
                     Bp[s] + (size_t)(k0 + r) * N + bn + c);
            }
        }
        cp_commit();
    };

    const int nkt = K / BK;
    load_tiles(0, 0);

    for (int kt = 0; kt < nkt; kt++) {
        const int st = kt & 1;
        if (kt + 1 < nkt) {
            load_tiles((kt + 1) * BK, (kt + 1) & 1);
            cp_wait<1>();
        } else {
            cp_wait<0>();
        }
        __syncthreads();

#pragma unroll
        for (int kk = 0; kk < BK; kk += 16) {
            uint32_t bfr[2][NS][4];
#pragma unroll
            for (int p = 0; p < 2; p++) {
                const int row = kk + (lane & 7) + (((lane >> 3) & 1) << 3);
                const int col = wn + p * 16 + ((lane >> 4) << 3);
#pragma unroll
                for (int s = 0; s < NS; s++)
                    ldm_x4_t(bfr[p][s][0], bfr[p][s][1], bfr[p][s][2], bfr[p][s][3],
                             sBaddr(st, s) + (uint32_t)(row * (128 + 8) + col) * 2u);
            }
#pragma unroll
            for (int mi = 0; mi < 4; mi++) {
                const int row = wm + mi * 16 + (lane & 15);
                const int col = kk + ((lane >> 4) << 3);
                uint32_t afr[NS][4];
#pragma unroll
                for (int s = 0; s < NS; s++)
                    ldm_x4(afr[s][0], afr[s][1], afr[s][2], afr[s][3],
                           sAaddr(st, s) + (uint32_t)(row * (BK + 8) + col) * 2u);
#pragma unroll
                for (int ni = 0; ni < 4; ni++) {
                    const int p = ni >> 1, q = (ni & 1) * 2;
                    // hi*hi
                    mma16816h(acc[mi][ni][0], acc[mi][ni][1], acc[mi][ni][2], acc[mi][ni][3],
                              afr[0][0], afr[0][1], afr[0][2], afr[0][3],
                              bfr[p][0][q], bfr[p][0][q + 1]);
                    if (NS == 2) {
                        // hi*lo
                        mma16816h(acc[mi][ni][0], acc[mi][ni][1], acc[mi][ni][2], acc[mi][ni][3],
                                  afr[0][0], afr[0][1], afr[0][2], afr[0][3],
                                  bfr[p][1][q], bfr[p][1][q + 1]);
                        // lo*hi
                        mma16816h(acc[mi][ni][0], acc[mi][ni][1], acc[mi][ni][2], acc[mi][ni][3],
                                  afr[1][0], afr[1][1], afr[1][2], afr[1][3],
                                  bfr[p][0][q], bfr[p][0][q + 1]);
                    }
                }
            }
        }
        __syncthreads();
    }

    // epilogue
#pragma unroll
    for (int mi = 0; mi < 4; mi++) {
#pragma unroll
        for (int ni = 0; ni < 4; ni++) {
            const int col = bn + wn + ni * 8 + (lane & 3) * 2;
            const float b0 = bias[col + 0];
            const float b1 = bias[col + 1];
            const long long r0 = bm + wm + mi * 16 + (lane >> 2);
            const long long r1 = r0 + 8;
            float v[4];
            v[0] = acc[mi][ni][0] + b0;
            v[1] = acc[mi][ni][1] + b1;
            v[2] = acc[mi][ni][2] + b0;
            v[3] = acc[mi][ni][3] + b1;
            if (RELU) {
#pragma unroll
                for (int t = 0; t < 4; t++) v[t] = fmaxf(v[t], 0.0f);
            }
            if (OUTM == 1) {
                __half2 h0 = __floats2half2_rn(v[0], v[1]);
                __half2 h1 = __floats2half2_rn(v[2], v[3]);
                __half2 l0 = __floats2half2_rn(v[0] - __half2float(__low2half(h0)),
                                               v[1] - __half2float(__high2half(h0)));
                __half2 l1 = __floats2half2_rn(v[2] - __half2float(__low2half(h1)),
                                               v[3] - __half2float(__high2half(h1)));
                *(__half2*)&C0[r0 * N + col] = h0;
                *(__half2*)&C0[r1 * N + col] = h1;
                *(__half2*)&C1[r0 * N + col] = l0;
                *(__half2*)&C1[r1 * N + col] = l1;
            } else if (OUTM == 2) {
                *(__half2*)&C0[r0 * N + col] = __floats2half2_rn(v[0], v[1]);
                *(__half2*)&C0[r1 * N + col] = __floats2half2_rn(v[2], v[3]);
            } else {
                *(float2*)&Cf[r0 * N + col] = make_float2(v[0], v[1]);
                *(float2*)&Cf[r1 * N + col] = make_float2(v[2], v[3]);
            }
        }
    }
}

// ---------------- fp32 SGEMM TRANSB (distance GEMM only; fp32-exact) ----------------
__global__ __launch_bounds__(256, 2)
void sgemm_tb_kernel(const float* __restrict__ A, const float* __restrict__ Bm,
                     float* __restrict__ C, int M, int N, int K)
{
    const int BM = 128, BN = 128, BK = 16;
    __shared__ float As[BK][BM + 4];
    __shared__ float Bs[BK][BN + 4];

    const int bm = blockIdx.y * BM;
    const int bn = blockIdx.x * BN;
    const int tid = threadIdx.x;
    const int tr = (tid / 16) * 8;
    const int tc = (tid % 16) * 8;

    float acc[8][8];
#pragma unroll
    for (int i = 0; i < 8; i++)
#pragma unroll
        for (int j = 0; j < 8; j++) acc[i][j] = 0.0f;

    const int arow = tid >> 2;
    const int acol = (tid & 3) * 4;

    for (int k0 = 0; k0 < K; k0 += BK) {
#pragma unroll
        for (int s = 0; s < 2; s++) {
            const int r = arow + s * 64;
            float4 v = *(const float4*)&A[(long long)(bm + r) * K + k0 + acol];
            As[acol + 0][r] = v.x;
            As[acol + 1][r] = v.y;
            As[acol + 2][r] = v.z;
            As[acol + 3][r] = v.w;
        }
#pragma unroll
        for (int s = 0; s < 2; s++) {
            const int n = arow + s * 64;
            float4 v = *(const float4*)&Bm[(long long)(bn + n) * K + k0 + acol];
            Bs[acol + 0][n] = v.x;
            Bs[acol + 1][n] = v.y;
            Bs[acol + 2][n] = v.z;
            Bs[acol + 3][n] = v.w;
        }
        __syncthreads();

#pragma unroll
        for (int kk = 0; kk < BK; kk++) {
            float ra[8], rb[8];
#pragma unroll
            for (int i = 0; i < 8; i++) ra[i] = As[kk][tr + i];
#pragma unroll
            for (int j = 0; j < 8; j++) rb[j] = Bs[kk][tc + j];
#pragma unroll
            for (int i = 0; i < 8; i++)
#pragma unroll
                for (int j = 0; j < 8; j++)
                    acc[i][j] = fmaf(ra[i], rb[j], acc[i][j]);
        }
        __syncthreads();
    }

#pragma unroll
    for (int i = 0; i < 8; i++) {
        const long long row = bm + tr + i;
#pragma unroll
        for (int j = 0; j < 8; j += 4) {
            float4 v = make_float4(acc[i][j], acc[i][j+1], acc[i][j+2], acc[i][j+3]);
            *(float4*)&C[row * N + bn + tc + j] = v;
        }
    }
}

// ---------------- conversions ----------------
__global__ void f2h2_kernel(const float* __restrict__ in,
                            __half* __restrict__ oh,
                            __half* __restrict__ ol, int n4)
{
    const int i = blockIdx.x * blockDim.x + threadIdx.x;
    if (i >= n4) return;
    float4 v = *(const float4*)&in[i * 4];
    __half2 h0 = __floats2half2_rn(v.x, v.y);
    __half2 h1 = __floats2half2_rn(v.z, v.w);
    __half2 l0 = __floats2half2_rn(v.x - __half2float(__low2half(h0)),
                                   v.y - __half2float(__high2half(h0)));
    __half2 l1 = __floats2half2_rn(v.z - __half2float(__low2half(h1)),
                                   v.w - __half2float(__high2half(h1)));
    *(__half2*)&oh[i * 4 + 0] = h0;
    *(__half2*)&oh[i * 4 + 2] = h1;
    *(__half2*)&ol[i * 4 + 0] = l0;
    *(__half2*)&ol[i * 4 + 2] = l1;
}

__global__ void f2h1_kernel(const float* __restrict__ in,
                            __half* __restrict__ oh, int n4)
{
    const int i = blockIdx.x * blockDim.x + threadIdx.x;
    if (i >= n4) return;
    float4 v = *(const float4*)&in[i * 4];
    *(__half2*)&oh[i * 4 + 0] = __floats2half2_rn(v.x, v.y);
    *(__half2*)&oh[i * 4 + 2] = __floats2half2_rn(v.z, v.w);
}

// ---------------- row squared-norms (256-wide rows, warp per row) ----------------
__global__ void rownorm256_kernel(const float* __restrict__ X, float* __restrict__ out,
                                  int rows)
{
    const int gw = (blockIdx.x * blockDim.x + threadIdx.x) >> 5;
    const int lane = threadIdx.x & 31;
    if (gw >= rows) return;
    const float* r = X + (long long)gw * 256;
    float a = 0.0f;
#pragma unroll
    for (int i = 0; i < 8; i++) {
        float v = r[lane + i * 32];
        a = fmaf(v, v, a);
    }
#pragma unroll
    for (int o = 16; o > 0; o >>= 1) a += __shfl_xor_sync(0xffffffffu, a, o);
    if (lane == 0) out[gw] = a;
}

// ---------------- argmin + gather + straight-through + row loss ----------------
__global__ void argmin_quant_kernel(const float* __restrict__ S,
                                    const float* __restrict__ z,
                                    const float* __restrict__ codebook,
                                    const float* __restrict__ cnorm,
                                    const float* __restrict__ znorm,
                                    float* __restrict__ out_qst,
                                    __half* __restrict__ out_qh,
                                    float* __restrict__ out_idx,
                                    float* __restrict__ rowloss)
{
    const int b = blockIdx.x;
    const int tid = threadIdx.x;   // 256 threads
    const float zn = znorm[b];

    float bestv = __int_as_float(0x7f800000);
    int besti = 0x7fffffff;
#pragma unroll
    for (int s = 0; s < K_CODES / 256; s++) {
        const int k = tid + s * 256;
        const float t = zn + cnorm[k];
        const float score = t - 2.0f * S[(long long)b * K_CODES + k];
        if (score < bestv) { bestv = score; besti = k; }
    }

    __shared__ float sv[256];
    __shared__ int   si[256];
    sv[tid] = bestv; si[tid] = besti;
    __syncthreads();
#pragma unroll
    for (int s = 128; s > 0; s >>= 1) {
        if (tid < s) {
            const float v2 = sv[tid + s];
            const int   i2 = si[tid + s];
            if (v2 < sv[tid] || (v2 == sv[tid] && i2 < si[tid])) {
                sv[tid] = v2; si[tid] = i2;
            }
        }
        __syncthreads();
    }
    const int idx = si[0];
    if (tid == 0) out_idx[b] = (float)idx;

    const float q = codebook[(long long)idx * D_CODE + tid];
    const float zv = z[(long long)b * D_CODE + tid];
    const float d = q - zv;
    const float qstv = zv + d;
    out_qst[(long long)b * D_CODE + tid] = qstv;
    out_qh[(long long)b * D_CODE + tid] = __float2half_rn(qstv);
    __syncthreads();
    sv[tid] = d * d;
    __syncthreads();
#pragma unroll
    for (int s = 128; s > 0; s >>= 1) {
        if (tid < s) sv[tid] += sv[tid + s];
        __syncthreads();
    }
    if (tid == 0) rowloss[b] = sv[0];
}

__global__ void loss_final_kernel(const float* __restrict__ rowloss,
                                  float* __restrict__ out_loss)
{
    __shared__ float s[1024];
    const int tid = threadIdx.x;
    float a = 0.0f;
    for (int i = tid; i < B_ROWS; i += 1024) a += rowloss[i];
    s[tid] = a;
    __syncthreads();
#pragma unroll
    for (int t = 512; t > 0; t >>= 1) {
        if (tid < t) s[tid] += s[tid + t];
        __syncthreads();
    }
    if (tid == 0) *out_loss = s[0] * (1.25f / (float)(B_ROWS * D_CODE));
}

// ---------------- launch ----------------
template<typename T>
static inline T* sym(const void* s) {
    void* p = nullptr;
    cudaGetSymbolAddress(&p, s);
    return (T*)p;
}

#define NS2_SMEM (2 * 37888)   // 75776 B
#define NS1_SMEM (37888)       // 37888 B

extern "C" void kernel_launch(void* const* d_in, const int* in_sizes, int n_in,
                              void* d_out, int out_size)
{
    const float* x    = (const float*)d_in[0];
    const float* eW1  = (const float*)d_in[1];
    const float* eb1  = (const float*)d_in[2];
    const float* eW2  = (const float*)d_in[3];
    const float* eb2  = (const float*)d_in[4];
    const float* eW3  = (const float*)d_in[5];
    const float* eb3  = (const float*)d_in[6];
    const float* cb   = (const float*)d_in[7];
    const float* dW1  = (const float*)d_in[8];
    const float* db1  = (const float*)d_in[9];
    const float* dW2  = (const float*)d_in[10];
    const float* db2  = (const float*)d_in[11];
    const float* dW3  = (const float*)d_in[12];
    const float* db3  = (const float*)d_in[13];

    float* out   = (float*)d_out;
    float* recon = out;
    float* qst   = out + QST_OFF;
    float* lossp = out + LOSS_OFF;
    float* idxp  = out + IDX_OFF;

    float* z  = sym<float>(g_z);
    float* S  = sym<float>(g_S);
    float* cn = sym<float>(g_cnorm);
    float* zn = sym<float>(g_znorm);
    float* rl = sym<float>(g_rowloss);

    __half *x2[2], *h12[2], *h22[2], *e1w[2], *e2w[2], *e3w[2];
    __half* base;
    base = sym<__half>(g_x2);  for (int s = 0; s < 2; s++) x2[s]  = base + (size_t)s * B_ROWS * D_IN;
    base = sym<__half>(g_h12); for (int s = 0; s < 2; s++) h12[s] = base + (size_t)s * B_ROWS * H1DIM;
    base = sym<__half>(g_h22); for (int s = 0; s < 2; s++) h22[s] = base + (size_t)s * B_ROWS * H2DIM;
    base = sym<__half>(g_e1w); for (int s = 0; s < 2; s++) e1w[s] = base + (size_t)s * D_IN * H1DIM;
    base = sym<__half>(g_e2w); for (int s = 0; s < 2; s++) e2w[s] = base + (size_t)s * H1DIM * H2DIM;
    base = sym<__half>(g_e3w); for (int s = 0; s < 2; s++) e3w[s] = base + (size_t)s * H2DIM * D_CODE;

    __half* q1  = sym<__half>(g_q1);
    __half* a1h = sym<__half>(g_a1h);
    __half* a2h = sym<__half>(g_a2h);
    __half* d1w = sym<__half>(g_d1w);
    __half* d2w = sym<__half>(g_d2w);
    __half* d3w = sym<__half>(g_d3w);

    // dynamic smem opt-in (host-side attribute, idempotent)
    cudaFuncSetAttribute(hgemm_kernel<2, true,  1>, cudaFuncAttributeMaxDynamicSharedMemorySize, NS2_SMEM);
    cudaFuncSetAttribute(hgemm_kernel<2, false, 0>, cudaFuncAttributeMaxDynamicSharedMemorySize, NS2_SMEM);
    cudaFuncSetAttribute(hgemm_kernel<1, true,  2>, cudaFuncAttributeMaxDynamicSharedMemorySize, NS1_SMEM);
    cudaFuncSetAttribute(hgemm_kernel<1, false, 0>, cudaFuncAttributeMaxDynamicSharedMemorySize, NS1_SMEM);

    dim3 blk(256);

    // conversions: encoder split-2, decoder single fp16
    f2h2_kernel<<<(B_ROWS * D_IN  / 4 + 255) / 256, 256>>>(x,   x2[0],  x2[1],  B_ROWS * D_IN / 4);
    f2h2_kernel<<<(D_IN  * H1DIM / 4 + 255) / 256, 256>>>(eW1, e1w[0], e1w[1], D_IN * H1DIM / 4);
    f2h2_kernel<<<(H1DIM * H2DIM / 4 + 255) / 256, 256>>>(eW2, e2w[0], e2w[1], H1DIM * H2DIM / 4);
    f2h2_kernel<<<(H2DIM * D_CODE/ 4 + 255) / 256, 256>>>(eW3, e3w[0], e3w[1], H2DIM * D_CODE / 4);
    f2h1_kernel<<<(D_CODE * H2DIM / 4 + 255) / 256, 256>>>(dW1, d1w, D_CODE * H2DIM / 4);
    f2h1_kernel<<<(H2DIM * H1DIM / 4 + 255) / 256, 256>>>(dW2, d2w, H2DIM * H1DIM / 4);
    f2h1_kernel<<<(H1DIM * D_IN  / 4 + 255) / 256, 256>>>(dW3, d3w, H1DIM * D_IN / 4);
    rownorm256_kernel<<<K_CODES * 32 / 256, 256>>>(cb, cn, K_CODES);

    // encoder: split-fp16, 3 products (~2^-22; argmin-safe)
    hgemm_kernel<2, true, 1><<<dim3(H1DIM/128, B_ROWS/128), blk, NS2_SMEM>>>(
        x2[0], x2[1], e1w[0], e1w[1], eb1, h12[0], h12[1], nullptr, B_ROWS, H1DIM, D_IN);
    hgemm_kernel<2, true, 1><<<dim3(H2DIM/128, B_ROWS/128), blk, NS2_SMEM>>>(
        h12[0], h12[1], e2w[0], e2w[1], eb2, h22[0], h22[1], nullptr, B_ROWS, H2DIM, H1DIM);
    hgemm_kernel<2, false, 0><<<dim3(D_CODE/128, B_ROWS/128), blk, NS2_SMEM>>>(
        h22[0], h22[1], e3w[0], e3w[1], eb3, nullptr, nullptr, z, B_ROWS, D_CODE, H2DIM);

    // z norms + distance GEMM (fp32-exact)
    rownorm256_kernel<<<B_ROWS * 32 / 256, 256>>>(z, zn, B_ROWS);
    sgemm_tb_kernel<<<dim3(K_CODES/128, B_ROWS/128), 256>>>(z, cb, S, B_ROWS, K_CODES, D_CODE);

    // argmin + gather + straight-through + row loss (+ fp16 qst for decoder)
    argmin_quant_kernel<<<B_ROWS, 256>>>(S, z, cb, cn, zn, qst, q1, idxp, rl);
    loss_final_kernel<<<1, 1024>>>(rl, lossp);

    // decoder: single fp16 (~2e-4 on recon; budget 1e-3)
    hgemm_kernel<1, true, 2><<<dim3(H2DIM/128, B_ROWS/128), blk, NS1_SMEM>>>(
        q1, nullptr, d1w, nullptr, db1, a1h, nullptr, nullptr, B_ROWS, H2DIM, D_CODE);
    hgemm_kernel<1, true, 2><<<dim3(H1DIM/128, B_ROWS/128), blk, NS1_SMEM>>>(
        a1h, nullptr, d2w, nullptr, db2, a2h, nullptr, nullptr, B_ROWS, H1DIM, H2DIM);
    hgemm_kernel<1, false, 0><<<dim3(D_IN/128, B_ROWS/128), blk, NS1_SMEM>>>(
        a2h, nullptr, d3w, nullptr, db3, nullptr, nullptr, recon, B_ROWS, D_IN, H1DIM);
}

// round 17
// speedup vs baseline: 3.6852x; 1.0677x over previous
#include <cuda_runtime.h>
#include <cuda_fp16.h>
#include <cstdint>

// ---------------- problem dims ----------------
#define B_ROWS 16384
#define D_IN   1024
#define H1DIM  2048
#define H2DIM  1024
#define D_CODE 256
#define K_CODES 1024

// output layout (f32, concatenated): recon | quantized_st | loss | indices
#define QST_OFF     (16777216)
#define LOSS_OFF    (16777216 + 4194304)                // 20971520
#define IDX_OFF     (20971521)

// ---------------- scratch (device globals; no allocation allowed) ----------------
__device__ float g_z [B_ROWS * D_CODE];   // 16 MB
__device__ float g_S [B_ROWS * K_CODES];  // 64 MB  (z @ codebook^T)
__device__ float g_cnorm[K_CODES];
__device__ float g_znorm[B_ROWS];
__device__ float g_rowloss[B_ROWS];

// encoder: split-2 fp16 (hi/lo; 3-product GEMM => ~2^-22 relative precision)
__device__ __half g_x2 [2][B_ROWS * D_IN];
__device__ __half g_h12[2][B_ROWS * H1DIM];
__device__ __half g_h22[2][B_ROWS * H2DIM];
__device__ __half g_e1w[2][D_IN  * H1DIM];
__device__ __half g_e2w[2][H1DIM * H2DIM];
__device__ __half g_e3w[2][H2DIM * D_CODE];
// distance path: split z and transposed-split codebook
__device__ __half g_z2 [2][B_ROWS * D_CODE];
__device__ __half g_cbt[2][D_CODE * K_CODES];

// decoder: single fp16 (1-product GEMM => ~2e-4 on recon; budget 1e-3)
__device__ __half g_q1 [B_ROWS * D_CODE];
__device__ __half g_a1h[B_ROWS * H2DIM];
__device__ __half g_a2h[B_ROWS * H1DIM];
__device__ __half g_d1w[D_CODE * H2DIM];
__device__ __half g_d2w[H2DIM * H1DIM];
__device__ __half g_d3w[H1DIM * D_IN];

// ---------------- helpers ----------------
static __device__ __forceinline__ uint32_t smem_u32(const void* p) {
    return (uint32_t)__cvta_generic_to_shared(p);
}
static __device__ __forceinline__ void cp16(uint32_t dst, const void* src) {
    asm volatile("cp.async.cg.shared.global [%0], [%1], 16;\n" :: "r"(dst), "l"(src));
}
static __device__ __forceinline__ void cp_commit() {
    asm volatile("cp.async.commit_group;\n");
}
template<int N> static __device__ __forceinline__ void cp_wait() {
    asm volatile("cp.async.wait_group %0;\n" :: "n"(N));
}
static __device__ __forceinline__ void ldm_x4(uint32_t& r0, uint32_t& r1, uint32_t& r2, uint32_t& r3, uint32_t a) {
    asm volatile("ldmatrix.sync.aligned.m8n8.x4.shared.b16 {%0,%1,%2,%3}, [%4];"
                 : "=r"(r0), "=r"(r1), "=r"(r2), "=r"(r3) : "r"(a));
}
static __device__ __forceinline__ void ldm_x4_t(uint32_t& r0, uint32_t& r1, uint32_t& r2, uint32_t& r3, uint32_t a) {
    asm volatile("ldmatrix.sync.aligned.m8n8.x4.trans.shared.b16 {%0,%1,%2,%3}, [%4];"
                 : "=r"(r0), "=r"(r1), "=r"(r2), "=r"(r3) : "r"(a));
}
static __device__ __forceinline__ void mma16816h(float& c0, float& c1, float& c2, float& c3,
                                                 uint32_t a0, uint32_t a1, uint32_t a2, uint32_t a3,
                                                 uint32_t b0, uint32_t b1) {
    asm volatile("mma.sync.aligned.m16n8k16.row.col.f32.f16.f16.f32 "
                 "{%0,%1,%2,%3}, {%4,%5,%6,%7}, {%8,%9}, {%0,%1,%2,%3};"
                 : "+f"(c0), "+f"(c1), "+f"(c2), "+f"(c3)
                 : "r"(a0), "r"(a1), "r"(a2), "r"(a3), "r"(b0), "r"(b1));
}

// ---------------- fp16 tensor-core GEMM ----------------
// NS=2: 3-product hi/lo split (~2^-22).  NS=1: plain fp16.
// A [M,K] row-major, B [K,N] row-major.
// OUTM: 0 = fp32 to Cf, 1 = split hi/lo to C0/C1, 2 = single fp16 to C0,
//       3 = fp32 to Cf AND split hi/lo to C0/C1.
// BIASF: whether bias is added.
template<int NS, bool RELU, int OUTM, bool BIASF>
__global__ __launch_bounds__(256, 2)
void hgemm_kernel(const __half* __restrict__ A0, const __half* __restrict__ A1,
                  const __half* __restrict__ B0, const __half* __restrict__ B1,
                  const float* __restrict__ bias,
                  __half* __restrict__ C0, __half* __restrict__ C1,
                  float* __restrict__ Cf,
                  int M, int N, int K)
{
    const int BK = 32;
    const int AT = 128 * (BK + 8);   // 5120 elems per A split tile
    const int BT = BK * (128 + 8);   // 4352 elems per B split tile
    const int STG = NS * (AT + BT);  // per-stage elems

    extern __shared__ __half dsm[];
    const uint32_t sbase = smem_u32(dsm);

    const int bm = blockIdx.y * 128;
    const int bn = blockIdx.x * 128;
    const int tid = threadIdx.x;
    const int lane = tid & 31;
    const int wid = tid >> 5;
    const int wm = (wid >> 2) * 64;   // 2 warps in m
    const int wn = (wid & 3) * 32;    // 4 warps in n

    const __half* Ap[2] = {A0, A1};
    const __half* Bp[2] = {B0, B1};

    float acc[4][4][4];
#pragma unroll
    for (int i = 0; i < 4; i++)
#pragma unroll
        for (int j = 0; j < 4; j++)
#pragma unroll
            for (int q = 0; q < 4; q++) acc[i][j][q] = 0.0f;

    auto sAaddr = [&](int st, int s) -> uint32_t { return sbase + (uint32_t)(st * STG + s * AT) * 2u; };
    auto sBaddr = [&](int st, int s) -> uint32_t { return sbase + (uint32_t)(st * STG + NS * AT + s * BT) * 2u; };

    auto load_tiles = [&](int k0, int st) {
#pragma unroll
        for (int s = 0; s < NS; s++) {
#pragma unroll
            for (int t = 0; t < 2; t++) {
                const int id = tid + t * 256;
                const int r = id >> 2, c = (id & 3) * 8;
                cp16(sAaddr(st, s) + (uint32_t)(r * (BK + 8) + c) * 2u,
                     Ap[s] + (size_t)(bm + r) * K + k0 + c);
            }
#pragma unroll
            for (int t = 0; t < 2; t++) {
                const int id = tid + t * 256;
                const int r = id >> 4, c = (id & 15) * 8;
                cp16(sBaddr(st, s) + (uint32_t)(r * (128 + 8) + c) * 2u,
                     Bp[s] + (size_t)(k0 + r) * N + bn + c);
            }
        }
        cp_commit();
    };

    const int nkt = K / BK;
    load_tiles(0, 0);

    for (int kt = 0; kt < nkt; kt++) {
        const int st = kt & 1;
        if (kt + 1 < nkt) {
            load_tiles((kt + 1) * BK, (kt + 1) & 1);
            cp_wait<1>();
        } else {
            cp_wait<0>();
        }
        __syncthreads();

#pragma unroll
        for (int kk = 0; kk < BK; kk += 16) {
            uint32_t bfr[2][NS][4];
#pragma unroll
            for (int p = 0; p < 2; p++) {
                const int row = kk + (lane & 7) + (((lane >> 3) & 1) << 3);
                const int col = wn + p * 16 + ((lane >> 4) << 3);
#pragma unroll
                for (int s = 0; s < NS; s++)
                    ldm_x4_t(bfr[p][s][0], bfr[p][s][1], bfr[p][s][2], bfr[p][s][3],
                             sBaddr(st, s) + (uint32_t)(row * (128 + 8) + col) * 2u);
            }
#pragma unroll
            for (int mi = 0; mi < 4; mi++) {
                const int row = wm + mi * 16 + (lane & 15);
                const int col = kk + ((lane >> 4) << 3);
                uint32_t afr[NS][4];
#pragma unroll
                for (int s = 0; s < NS; s++)
                    ldm_x4(afr[s][0], afr[s][1], afr[s][2], afr[s][3],
                           sAaddr(st, s) + (uint32_t)(row * (BK + 8) + col) * 2u);
#pragma unroll
                for (int ni = 0; ni < 4; ni++) {
                    const int p = ni >> 1, q = (ni & 1) * 2;
                    // hi*hi
                    mma16816h(acc[mi][ni][0], acc[mi][ni][1], acc[mi][ni][2], acc[mi][ni][3],
                              afr[0][0], afr[0][1], afr[0][2], afr[0][3],
                              bfr[p][0][q], bfr[p][0][q + 1]);
                    if (NS == 2) {
                        // hi*lo
                        mma16816h(acc[mi][ni][0], acc[mi][ni][1], acc[mi][ni][2], acc[mi][ni][3],
                                  afr[0][0], afr[0][1], afr[0][2], afr[0][3],
                                  bfr[p][1][q], bfr[p][1][q + 1]);
                        // lo*hi
                        mma16816h(acc[mi][ni][0], acc[mi][ni][1], acc[mi][ni][2], acc[mi][ni][3],
                                  afr[1][0], afr[1][1], afr[1][2], afr[1][3],
                                  bfr[p][0][q], bfr[p][0][q + 1]);
                    }
                }
            }
        }
        __syncthreads();
    }

    // epilogue
#pragma unroll
    for (int mi = 0; mi < 4; mi++) {
#pragma unroll
        for (int ni = 0; ni < 4; ni++) {
            const int col = bn + wn + ni * 8 + (lane & 3) * 2;
            float b0 = 0.0f, b1 = 0.0f;
            if (BIASF) { b0 = bias[col + 0]; b1 = bias[col + 1]; }
            const long long r0 = bm + wm + mi * 16 + (lane >> 2);
            const long long r1 = r0 + 8;
            float v[4];
            v[0] = acc[mi][ni][0] + b0;
            v[1] = acc[mi][ni][1] + b1;
            v[2] = acc[mi][ni][2] + b0;
            v[3] = acc[mi][ni][3] + b1;
            if (RELU) {
#pragma unroll
                for (int t = 0; t < 4; t++) v[t] = fmaxf(v[t], 0.0f);
            }
            if (OUTM == 1 || OUTM == 3) {
                __half2 h0 = __floats2half2_rn(v[0], v[1]);
                __half2 h1 = __floats2half2_rn(v[2], v[3]);
                __half2 l0 = __floats2half2_rn(v[0] - __half2float(__low2half(h0)),
                                               v[1] - __half2float(__high2half(h0)));
                __half2 l1 = __floats2half2_rn(v[2] - __half2float(__low2half(h1)),
                                               v[3] - __half2float(__high2half(h1)));
                *(__half2*)&C0[r0 * N + col] = h0;
                *(__half2*)&C0[r1 * N + col] = h1;
                *(__half2*)&C1[r0 * N + col] = l0;
                *(__half2*)&C1[r1 * N + col] = l1;
            } else if (OUTM == 2) {
                *(__half2*)&C0[r0 * N + col] = __floats2half2_rn(v[0], v[1]);
                *(__half2*)&C0[r1 * N + col] = __floats2half2_rn(v[2], v[3]);
            }
            if (OUTM == 0 || OUTM == 3) {
                *(float2*)&Cf[r0 * N + col] = make_float2(v[0], v[1]);
                *(float2*)&Cf[r1 * N + col] = make_float2(v[2], v[3]);
            }
        }
    }
}

// ---------------- conversions ----------------
__global__ void f2h2_kernel(const float* __restrict__ in,
                            __half* __restrict__ oh,
                            __half* __restrict__ ol, int n4)
{
    const int i = blockIdx.x * blockDim.x + threadIdx.x;
    if (i >= n4) return;
    float4 v = *(const float4*)&in[i * 4];
    __half2 h0 = __floats2half2_rn(v.x, v.y);
    __half2 h1 = __floats2half2_rn(v.z, v.w);
    __half2 l0 = __floats2half2_rn(v.x - __half2float(__low2half(h0)),
                                   v.y - __half2float(__high2half(h0)));
    __half2 l1 = __floats2half2_rn(v.z - __half2float(__low2half(h1)),
                                   v.w - __half2float(__high2half(h1)));
    *(__half2*)&oh[i * 4 + 0] = h0;
    *(__half2*)&oh[i * 4 + 2] = h1;
    *(__half2*)&ol[i * 4 + 0] = l0;
    *(__half2*)&ol[i * 4 + 2] = l1;
}

__global__ void f2h1_kernel(const float* __restrict__ in,
                            __half* __restrict__ oh, int n4)
{
    const int i = blockIdx.x * blockDim.x + threadIdx.x;
    if (i >= n4) return;
    float4 v = *(const float4*)&in[i * 4];
    *(__half2*)&oh[i * 4 + 0] = __floats2half2_rn(v.x, v.y);
    *(__half2*)&oh[i * 4 + 2] = __floats2half2_rn(v.z, v.w);
}

// codebook: fp32 cb[K_CODES, D_CODE] -> split fp16 cb^T [D_CODE, K_CODES]
__global__ void cbsplit_t_kernel(const float* __restrict__ cb,
                                 __half* __restrict__ Th, __half* __restrict__ Tl)
{
    __shared__ float tile[32][33];
    const int k0 = blockIdx.x * 32;   // code index
    const int d0 = blockIdx.y * 32;   // dim index
    const int tx = threadIdx.x, ty = threadIdx.y;   // (32, 8)
#pragma unroll
    for (int i = ty; i < 32; i += 8)
        tile[i][tx] = cb[(size_t)(k0 + i) * D_CODE + d0 + tx];
    __syncthreads();
#pragma unroll
    for (int i = ty; i < 32; i += 8) {
        const float v = tile[tx][i];   // cb[k0+tx][d0+i]
        const __half h = __float2half_rn(v);
        Th[(size_t)(d0 + i) * K_CODES + k0 + tx] = h;
        Tl[(size_t)(d0 + i) * K_CODES + k0 + tx] = __float2half_rn(v - __half2float(h));
    }
}

// ---------------- row squared-norms (256-wide rows, warp per row) ----------------
__global__ void rownorm256_kernel(const float* __restrict__ X, float* __restrict__ out,
                                  int rows)
{
    const int gw = (blockIdx.x * blockDim.x + threadIdx.x) >> 5;
    const int lane = threadIdx.x & 31;
    if (gw >= rows) return;
    const float* r = X + (long long)gw * 256;
    float a = 0.0f;
#pragma unroll
    for (int i = 0; i < 8; i++) {
        float v = r[lane + i * 32];
        a = fmaf(v, v, a);
    }
#pragma unroll
    for (int o = 16; o > 0; o >>= 1) a += __shfl_xor_sync(0xffffffffu, a, o);
    if (lane == 0) out[gw] = a;
}

// ---------------- argmin + gather + straight-through + row loss ----------------
__global__ void argmin_quant_kernel(const float* __restrict__ S,
                                    const float* __restrict__ z,
                                    const float* __restrict__ codebook,
                                    const float* __restrict__ cnorm,
                                    const float* __restrict__ znorm,
                                    float* __restrict__ out_qst,
                                    __half* __restrict__ out_qh,
                                    float* __restrict__ out_idx,
                                    float* __restrict__ rowloss)
{
    const int b = blockIdx.x;
    const int tid = threadIdx.x;   // 256 threads
    const float zn = znorm[b];

    float bestv = __int_as_float(0x7f800000);
    int besti = 0x7fffffff;
#pragma unroll
    for (int s = 0; s < K_CODES / 256; s++) {
        const int k = tid + s * 256;
        const float t = zn + cnorm[k];
        const float score = t - 2.0f * S[(long long)b * K_CODES + k];
        if (score < bestv) { bestv = score; besti = k; }
    }

    __shared__ float sv[256];
    __shared__ int   si[256];
    sv[tid] = bestv; si[tid] = besti;
    __syncthreads();
#pragma unroll
    for (int s = 128; s > 0; s >>= 1) {
        if (tid < s) {
            const float v2 = sv[tid + s];
            const int   i2 = si[tid + s];
            if (v2 < sv[tid] || (v2 == sv[tid] && i2 < si[tid])) {
                sv[tid] = v2; si[tid] = i2;
            }
        }
        __syncthreads();
    }
    const int idx = si[0];
    if (tid == 0) out_idx[b] = (float)idx;

    const float q = codebook[(long long)idx * D_CODE + tid];
    const float zv = z[(long long)b * D_CODE + tid];
    const float d = q - zv;
    const float qstv = zv + d;
    out_qst[(long long)b * D_CODE + tid] = qstv;
    out_qh[(long long)b * D_CODE + tid] = __float2half_rn(qstv);
    __syncthreads();
    sv[tid] = d * d;
    __syncthreads();
#pragma unroll
    for (int s = 128; s > 0; s >>= 1) {
        if (tid < s) sv[tid] += sv[tid + s];
        __syncthreads();
    }
    if (tid == 0) rowloss[b] = sv[0];
}

__global__ void loss_final_kernel(const float* __restrict__ rowloss,
                                  float* __restrict__ out_loss)
{
    __shared__ float s[1024];
    const int tid = threadIdx.x;
    float a = 0.0f;
    for (int i = tid; i < B_ROWS; i += 1024) a += rowloss[i];
    s[tid] = a;
    __syncthreads();
#pragma unroll
    for (int t = 512; t > 0; t >>= 1) {
        if (tid < t) s[tid] += s[tid + t];
        __syncthreads();
    }
    if (tid == 0) *out_loss = s[0] * (1.25f / (float)(B_ROWS * D_CODE));
}

// ---------------- launch ----------------
template<typename T>
static inline T* sym(const void* s) {
    void* p = nullptr;
    cudaGetSymbolAddress(&p, s);
    return (T*)p;
}

#define NS2_SMEM (2 * 37888)   // 75776 B
#define NS1_SMEM (37888)       // 37888 B

extern "C" void kernel_launch(void* const* d_in, const int* in_sizes, int n_in,
                              void* d_out, int out_size)
{
    const float* x    = (const float*)d_in[0];
    const float* eW1  = (const float*)d_in[1];
    const float* eb1  = (const float*)d_in[2];
    const float* eW2  = (const float*)d_in[3];
    const float* eb2  = (const float*)d_in[4];
    const float* eW3  = (const float*)d_in[5];
    const float* eb3  = (const float*)d_in[6];
    const float* cb   = (const float*)d_in[7];
    const float* dW1  = (const float*)d_in[8];
    const float* db1  = (const float*)d_in[9];
    const float* dW2  = (const float*)d_in[10];
    const float* db2  = (const float*)d_in[11];
    const float* dW3  = (const float*)d_in[12];
    const float* db3  = (const float*)d_in[13];

    float* out   = (float*)d_out;
    float* recon = out;
    float* qst   = out + QST_OFF;
    float* lossp = out + LOSS_OFF;
    float* idxp  = out + IDX_OFF;

    float* z  = sym<float>(g_z);
    float* S  = sym<float>(g_S);
    float* cn = sym<float>(g_cnorm);
    float* zn = sym<float>(g_znorm);
    float* rl = sym<float>(g_rowloss);

    __half *x2[2], *h12[2], *h22[2], *e1w[2], *e2w[2], *e3w[2], *z2[2], *cbt[2];
    __half* base;
    base = sym<__half>(g_x2);  for (int s = 0; s < 2; s++) x2[s]  = base + (size_t)s * B_ROWS * D_IN;
    base = sym<__half>(g_h12); for (int s = 0; s < 2; s++) h12[s] = base + (size_t)s * B_ROWS * H1DIM;
    base = sym<__half>(g_h22); for (int s = 0; s < 2; s++) h22[s] = base + (size_t)s * B_ROWS * H2DIM;
    base = sym<__half>(g_e1w); for (int s = 0; s < 2; s++) e1w[s] = base + (size_t)s * D_IN * H1DIM;
    base = sym<__half>(g_e2w); for (int s = 0; s < 2; s++) e2w[s] = base + (size_t)s * H1DIM * H2DIM;
    base = sym<__half>(g_e3w); for (int s = 0; s < 2; s++) e3w[s] = base + (size_t)s * H2DIM * D_CODE;
    base = sym<__half>(g_z2);  for (int s = 0; s < 2; s++) z2[s]  = base + (size_t)s * B_ROWS * D_CODE;
    base = sym<__half>(g_cbt); for (int s = 0; s < 2; s++) cbt[s] = base + (size_t)s * D_CODE * K_CODES;

    __half* q1  = sym<__half>(g_q1);
    __half* a1h = sym<__half>(g_a1h);
    __half* a2h = sym<__half>(g_a2h);
    __half* d1w = sym<__half>(g_d1w);
    __half* d2w = sym<__half>(g_d2w);
    __half* d3w = sym<__half>(g_d3w);

    // dynamic smem opt-in (host-side attribute, idempotent)
    cudaFuncSetAttribute(hgemm_kernel<2, true,  1, true >, cudaFuncAttributeMaxDynamicSharedMemorySize, NS2_SMEM);
    cudaFuncSetAttribute(hgemm_kernel<2, false, 3, true >, cudaFuncAttributeMaxDynamicSharedMemorySize, NS2_SMEM);
    cudaFuncSetAttribute(hgemm_kernel<2, false, 0, false>, cudaFuncAttributeMaxDynamicSharedMemorySize, NS2_SMEM);
    cudaFuncSetAttribute(hgemm_kernel<1, true,  2, true >, cudaFuncAttributeMaxDynamicSharedMemorySize, NS1_SMEM);
    cudaFuncSetAttribute(hgemm_kernel<1, false, 0, true >, cudaFuncAttributeMaxDynamicSharedMemorySize, NS1_SMEM);

    dim3 blk(256);

    // conversions: encoder split-2, decoder single fp16, codebook transpose-split
    f2h2_kernel<<<(B_ROWS * D_IN  / 4 + 255) / 256, 256>>>(x,   x2[0],  x2[1],  B_ROWS * D_IN / 4);
    f2h2_kernel<<<(D_IN  * H1DIM / 4 + 255) / 256, 256>>>(eW1, e1w[0], e1w[1], D_IN * H1DIM / 4);
    f2h2_kernel<<<(H1DIM * H2DIM / 4 + 255) / 256, 256>>>(eW2, e2w[0], e2w[1], H1DIM * H2DIM / 4);
    f2h2_kernel<<<(H2DIM * D_CODE/ 4 + 255) / 256, 256>>>(eW3, e3w[0], e3w[1], H2DIM * D_CODE / 4);
    f2h1_kernel<<<(D_CODE * H2DIM / 4 + 255) / 256, 256>>>(dW1, d1w, D_CODE * H2DIM / 4);
    f2h1_kernel<<<(H2DIM * H1DIM / 4 + 255) / 256, 256>>>(dW2, d2w, H2DIM * H1DIM / 4);
    f2h1_kernel<<<(H1DIM * D_IN  / 4 + 255) / 256, 256>>>(dW3, d3w, H1DIM * D_IN / 4);
    cbsplit_t_kernel<<<dim3(K_CODES/32, D_CODE/32), dim3(32, 8)>>>(cb, cbt[0], cbt[1]);
    rownorm256_kernel<<<K_CODES * 32 / 256, 256>>>(cb, cn, K_CODES);

    // encoder: split-fp16, 3 products (~2^-22; argmin-safe); layer 3 emits fp32 z + split z
    hgemm_kernel<2, true, 1, true><<<dim3(H1DIM/128, B_ROWS/128), blk, NS2_SMEM>>>(
        x2[0], x2[1], e1w[0], e1w[1], eb1, h12[0], h12[1], nullptr, B_ROWS, H1DIM, D_IN);
    hgemm_kernel<2, true, 1, true><<<dim3(H2DIM/128, B_ROWS/128), blk, NS2_SMEM>>>(
        h12[0], h12[1], e2w[0], e2w[1], eb2, h22[0], h22[1], nullptr, B_ROWS, H2DIM, H1DIM);
    hgemm_kernel<2, false, 3, true><<<dim3(D_CODE/128, B_ROWS/128), blk, NS2_SMEM>>>(
        h22[0], h22[1], e3w[0], e3w[1], eb3, z2[0], z2[1], z, B_ROWS, D_CODE, H2DIM);

    // z norms + distance GEMM (split-fp16 3-product; score err ~2e-8 << gaps ~1e-4)
    rownorm256_kernel<<<B_ROWS * 32 / 256, 256>>>(z, zn, B_ROWS);
    hgemm_kernel<2, false, 0, false><<<dim3(K_CODES/128, B_ROWS/128), blk, NS2_SMEM>>>(
        z2[0], z2[1], cbt[0], cbt[1], nullptr, nullptr, nullptr, S, B_ROWS, K_CODES, D_CODE);

    // argmin + gather + straight-through + row loss (+ fp16 qst for decoder)
    argmin_quant_kernel<<<B_ROWS, 256>>>(S, z, cb, cn, zn, qst, q1, idxp, rl);
    loss_final_kernel<<<1, 1024>>>(rl, lossp);

    // decoder: single fp16 (~2e-4 on recon; budget 1e-3)
    hgemm_kernel<1, true, 2, true><<<dim3(H2DIM/128, B_ROWS/128), blk, NS1_SMEM>>>(
        q1, nullptr, d1w, nullptr, db1, a1h, nullptr, nullptr, B_ROWS, H2DIM, D_CODE);
    hgemm_kernel<1, true, 2, true><<<dim3(H1DIM/128, B_ROWS/128), blk, NS1_SMEM>>>(
        a1h, nullptr, d2w, nullptr, db2, a2h, nullptr, nullptr, B_ROWS, H1DIM, H2DIM);
    hgemm_kernel<1, false, 0, true><<<dim3(D_IN/128, B_ROWS/128), blk, NS1_SMEM>>>(
        a2h, nullptr, d3w, nullptr, db3, nullptr, nullptr, recon, B_ROWS, D_IN, H1DIM);
}